// round 2
// baseline (speedup 1.0000x reference)
#include <cuda_runtime.h>
#include <cuda_bf16.h>
#include <cstdint>

// Problem constants
#define BATCH 16
#define CH    512
#define NTOK  1024          // H*W = 32*32
#define HID   2048          // 4*C
#define SCALE 0.04419417382415922f   // 512^-0.5

// Static device scratch (allocations are forbidden in kernel_launch)
__device__ float g_S[(size_t)BATCH * NTOK * NTOK];   // 64 MB  attention scores/probs
__device__ float g_O[(size_t)BATCH * NTOK * CH];     // 32 MB  attention output [B*N, C]
__device__ float g_H[(size_t)BATCH * NTOK * HID];    // 128 MB FFN hidden      [B*N, HID]

// ---------------------------------------------------------------------------
// Stage 1: S[b][n][m] = SCALE * sum_c X[b][c][n] * X[b][c][m]
// TN GEMM: both operands K-major (k stride = NTOK). 64x64 tile, 4x4/thread.
// ---------------------------------------------------------------------------
__global__ __launch_bounds__(256) void attn_scores_kernel(
    const float* __restrict__ x, float* __restrict__ S)
{
    const int bm = blockIdx.x, bn = blockIdx.y, b = blockIdx.z;
    const float* __restrict__ X = x + (size_t)b * CH * NTOK;
    float* __restrict__ Sb = S + (size_t)b * NTOK * NTOK;

    __shared__ float As[16][68];
    __shared__ float Bs[16][68];

    const int tx = threadIdx.x, ty = threadIdx.y;
    const int tid = ty * 16 + tx;
    const int lk = tid >> 4;          // 0..15 (k row of tile)
    const int li = (tid & 15) * 4;    // 0..60 (col, float4)

    float acc[4][4];
#pragma unroll
    for (int u = 0; u < 4; u++)
#pragma unroll
        for (int v = 0; v < 4; v++) acc[u][v] = 0.f;

    for (int k0 = 0; k0 < CH; k0 += 16) {
        *(float4*)&As[lk][li] = *(const float4*)&X[(size_t)(k0 + lk) * NTOK + bm * 64 + li];
        *(float4*)&Bs[lk][li] = *(const float4*)&X[(size_t)(k0 + lk) * NTOK + bn * 64 + li];
        __syncthreads();
#pragma unroll
        for (int kk = 0; kk < 16; kk++) {
            float4 a4 = *(float4*)&As[kk][ty * 4];
            float4 b4 = *(float4*)&Bs[kk][tx * 4];
            float a[4] = {a4.x, a4.y, a4.z, a4.w};
            float bb[4] = {b4.x, b4.y, b4.z, b4.w};
#pragma unroll
            for (int u = 0; u < 4; u++)
#pragma unroll
                for (int v = 0; v < 4; v++) acc[u][v] += a[u] * bb[v];
        }
        __syncthreads();
    }

#pragma unroll
    for (int u = 0; u < 4; u++) {
        float4 o;
        o.x = acc[u][0] * SCALE; o.y = acc[u][1] * SCALE;
        o.z = acc[u][2] * SCALE; o.w = acc[u][3] * SCALE;
        *(float4*)&Sb[(size_t)(bm * 64 + ty * 4 + u) * NTOK + bn * 64 + tx * 4] = o;
    }
}

// ---------------------------------------------------------------------------
// Stage 2: row softmax over 1024 elements, one block (256 thr) per row.
// ---------------------------------------------------------------------------
__global__ __launch_bounds__(256) void softmax_rows_kernel(float* __restrict__ S)
{
    float4* row = reinterpret_cast<float4*>(S + (size_t)blockIdx.x * NTOK);
    const int t = threadIdx.x;
    const int wid = t >> 5, lane = t & 31;

    float4 v = row[t];
    float m = fmaxf(fmaxf(v.x, v.y), fmaxf(v.z, v.w));
#pragma unroll
    for (int o = 16; o > 0; o >>= 1) m = fmaxf(m, __shfl_xor_sync(0xffffffffu, m, o));

    __shared__ float sred[8];
    __shared__ float sbc;
    if (!lane) sred[wid] = m;
    __syncthreads();
    if (t == 0) {
        float mm = sred[0];
#pragma unroll
        for (int i = 1; i < 8; i++) mm = fmaxf(mm, sred[i]);
        sbc = mm;
    }
    __syncthreads();
    m = sbc;

    v.x = __expf(v.x - m); v.y = __expf(v.y - m);
    v.z = __expf(v.z - m); v.w = __expf(v.w - m);
    float s = v.x + v.y + v.z + v.w;
#pragma unroll
    for (int o = 16; o > 0; o >>= 1) s += __shfl_xor_sync(0xffffffffu, s, o);
    __syncthreads();                     // protect sbc reuse
    if (!lane) sred[wid] = s;
    __syncthreads();
    if (t == 0) {
        float ss = 0.f;
#pragma unroll
        for (int i = 0; i < 8; i++) ss += sred[i];
        sbc = 1.0f / ss;
    }
    __syncthreads();
    float inv = sbc;
    v.x *= inv; v.y *= inv; v.z *= inv; v.w *= inv;
    row[t] = v;
}

// ---------------------------------------------------------------------------
// NT GEMM: C[i][j] = sum_k A[i*K+k] * B[j*K+k]  (+ epilogue per MODE)
// MODE 0: plain store C row-major [M,N]
// MODE 1: +bias, relu, store row-major
// MODE 2: +bias, store TRANSPOSED per batch ([B,C,N] layout) + residual add
// Batched via blockIdx.z with element strides sA/sB/sC.
// ---------------------------------------------------------------------------
template <int MODE>
__global__ __launch_bounds__(256) void gemm_nt_kernel(
    const float* __restrict__ A, const float* __restrict__ B, float* __restrict__ C,
    int M, int N, int K, size_t sA, size_t sB, size_t sC,
    const float* __restrict__ bias, const float* __restrict__ resid)
{
    const int z = blockIdx.z;
    A += (size_t)z * sA; B += (size_t)z * sB; C += (size_t)z * sC;

    __shared__ float As[16][68];
    __shared__ float Bs[16][68];
    __shared__ float T[(MODE == 2) ? 64 * 65 : 1];

    const int tx = threadIdx.x, ty = threadIdx.y;
    const int tid = ty * 16 + tx;
    const int lrow = tid >> 2;          // 0..63
    const int lkc  = (tid & 3) * 4;     // 0,4,8,12
    const int i0 = blockIdx.x * 64;
    const int j0 = blockIdx.y * 64;

    float acc[4][4];
#pragma unroll
    for (int u = 0; u < 4; u++)
#pragma unroll
        for (int v = 0; v < 4; v++) acc[u][v] = 0.f;

    for (int k0 = 0; k0 < K; k0 += 16) {
        float4 a = *(const float4*)&A[(size_t)(i0 + lrow) * K + k0 + lkc];
        float4 b = *(const float4*)&B[(size_t)(j0 + lrow) * K + k0 + lkc];
        As[lkc + 0][lrow] = a.x; As[lkc + 1][lrow] = a.y;
        As[lkc + 2][lrow] = a.z; As[lkc + 3][lrow] = a.w;
        Bs[lkc + 0][lrow] = b.x; Bs[lkc + 1][lrow] = b.y;
        Bs[lkc + 2][lrow] = b.z; Bs[lkc + 3][lrow] = b.w;
        __syncthreads();
#pragma unroll
        for (int kk = 0; kk < 16; kk++) {
            float4 a4 = *(float4*)&As[kk][ty * 4];
            float4 b4 = *(float4*)&Bs[kk][tx * 4];
            float av[4] = {a4.x, a4.y, a4.z, a4.w};
            float bv[4] = {b4.x, b4.y, b4.z, b4.w};
#pragma unroll
            for (int u = 0; u < 4; u++)
#pragma unroll
                for (int v = 0; v < 4; v++) acc[u][v] += av[u] * bv[v];
        }
        __syncthreads();
    }

    if (MODE == 0) {
#pragma unroll
        for (int u = 0; u < 4; u++) {
            float4 o; o.x = acc[u][0]; o.y = acc[u][1]; o.z = acc[u][2]; o.w = acc[u][3];
            *(float4*)&C[(size_t)(i0 + ty * 4 + u) * N + j0 + tx * 4] = o;
        }
    } else if (MODE == 1) {
        float bj[4];
#pragma unroll
        for (int v = 0; v < 4; v++) bj[v] = bias[j0 + tx * 4 + v];
#pragma unroll
        for (int u = 0; u < 4; u++) {
            float4 o;
            o.x = fmaxf(acc[u][0] + bj[0], 0.f);
            o.y = fmaxf(acc[u][1] + bj[1], 0.f);
            o.z = fmaxf(acc[u][2] + bj[2], 0.f);
            o.w = fmaxf(acc[u][3] + bj[3], 0.f);
            *(float4*)&C[(size_t)(i0 + ty * 4 + u) * N + j0 + tx * 4] = o;
        }
    } else {
        // MODE 2: bias + transpose through smem + residual; output layout [B, C, NTOK]
        float bj[4];
#pragma unroll
        for (int v = 0; v < 4; v++) bj[v] = bias[j0 + tx * 4 + v];
#pragma unroll
        for (int u = 0; u < 4; u++)
#pragma unroll
            for (int v = 0; v < 4; v++)
                T[(ty * 4 + u) * 65 + (tx * 4 + v)] = acc[u][v] + bj[v];
        __syncthreads();

        const int jl   = tid >> 2;          // 0..63: channel within tile
        const int iseg = (tid & 3) * 16;    // row segment (16 rows)
        const int gi = i0 + iseg;           // global row (= b*NTOK + n)
        const int b  = gi >> 10;            // /NTOK
        const int n  = gi & (NTOK - 1);
        const int ch = j0 + jl;
        const size_t base = (size_t)b * CH * NTOK + (size_t)ch * NTOK + n;
#pragma unroll
        for (int s = 0; s < 4; s++) {
            float4 r = *(const float4*)&resid[base + s * 4];
            float4 o;
            o.x = T[(iseg + s * 4 + 0) * 65 + jl] + r.x;
            o.y = T[(iseg + s * 4 + 1) * 65 + jl] + r.y;
            o.z = T[(iseg + s * 4 + 2) * 65 + jl] + r.z;
            o.w = T[(iseg + s * 4 + 3) * 65 + jl] + r.w;
            *(float4*)&C[base + s * 4] = o;
        }
    }
}

// ---------------------------------------------------------------------------
extern "C" void kernel_launch(void* const* d_in, const int* in_sizes, int n_in,
                              void* d_out, int out_size)
{
    const float* x  = (const float*)d_in[0];
    const float* w1 = (const float*)d_in[1];
    const float* b1 = (const float*)d_in[2];
    const float* w2 = (const float*)d_in[3];
    const float* b2 = (const float*)d_in[4];
    float* out = (float*)d_out;

    float *S, *O, *H;
    cudaGetSymbolAddress((void**)&S, g_S);
    cudaGetSymbolAddress((void**)&O, g_O);
    cudaGetSymbolAddress((void**)&H, g_H);

    dim3 blk(16, 16);

    // 1) scores S = SCALE * X^T X      [B, N, N]
    attn_scores_kernel<<<dim3(NTOK / 64, NTOK / 64, BATCH), blk>>>(x, S);

    // 2) softmax rows
    softmax_rows_kernel<<<BATCH * NTOK, 256>>>(S);

    // 3) O = P @ X^T                   [B*N, C]
    gemm_nt_kernel<0><<<dim3(NTOK / 64, CH / 64, BATCH), blk>>>(
        S, x, O, NTOK, CH, NTOK,
        (size_t)NTOK * NTOK, (size_t)CH * NTOK, (size_t)NTOK * CH, nullptr, nullptr);

    // 4) H = relu(O @ w1^T + b1)       [B*N, HID]
    gemm_nt_kernel<1><<<dim3(BATCH * NTOK / 64, HID / 64, 1), blk>>>(
        O, w1, H, BATCH * NTOK, HID, CH, 0, 0, 0, b1, nullptr);

    // 5) y = H @ w2^T + b2, transposed store + residual -> out [B, C, H, W]
    gemm_nt_kernel<2><<<dim3(BATCH * NTOK / 64, CH / 64, 1), blk>>>(
        H, w2, out, BATCH * NTOK, CH, HID, 0, 0, 0, b2, x);
}

// round 6
// speedup vs baseline: 3.3012x; 3.3012x over previous
#include <cuda_runtime.h>
#include <cuda_bf16.h>
#include <cstdint>

// Problem constants
#define BATCH 16
#define CH    512
#define NTOK  1024
#define HID   2048
#define SCALE 0.04419417382415922f   // 512^-0.5

// ---------------------------------------------------------------------------
// Static device scratch
// ---------------------------------------------------------------------------
__device__ float          g_S [(size_t)BATCH * NTOK * NTOK];   // fp32 scores
__device__ __nv_bfloat16  g_Ph[(size_t)BATCH * NTOK * NTOK];   // probs hi
__device__ __nv_bfloat16  g_Pl[(size_t)BATCH * NTOK * NTOK];   // probs lo
__device__ __nv_bfloat16  g_XTh[(size_t)BATCH * NTOK * CH];    // X^T [B,N,C]
__device__ __nv_bfloat16  g_XTl[(size_t)BATCH * NTOK * CH];
__device__ __nv_bfloat16  g_Xbh[(size_t)BATCH * CH * NTOK];    // X   [B,C,N]
__device__ __nv_bfloat16  g_Xbl[(size_t)BATCH * CH * NTOK];
__device__ __nv_bfloat16  g_Oh[(size_t)BATCH * NTOK * CH];     // attn out
__device__ __nv_bfloat16  g_Ol[(size_t)BATCH * NTOK * CH];
__device__ __nv_bfloat16  g_Hh[(size_t)BATCH * NTOK * HID];    // hidden
__device__ __nv_bfloat16  g_Hl[(size_t)BATCH * NTOK * HID];
__device__ __nv_bfloat16  g_w1h[(size_t)HID * CH];
__device__ __nv_bfloat16  g_w1l[(size_t)HID * CH];
__device__ __nv_bfloat16  g_w2h[(size_t)CH * HID];
__device__ __nv_bfloat16  g_w2l[(size_t)CH * HID];

// ---------------------------------------------------------------------------
// Helpers (all baseline PTX: sm_80-class, valid on compute_103)
// ---------------------------------------------------------------------------
__device__ __forceinline__ uint32_t smem_u32(const void* p) {
    uint32_t a;
    asm("{ .reg .u64 t; cvta.to.shared.u64 t, %1; cvt.u32.u64 %0, t; }" : "=r"(a) : "l"(p));
    return a;
}
__device__ __forceinline__ void cpa16(uint32_t d, const void* s) {
    asm volatile("cp.async.cg.shared.global [%0], [%1], 16;" :: "r"(d), "l"(s));
}
#define CP_COMMIT() asm volatile("cp.async.commit_group;" ::: "memory")
#define CP_WAIT1()  asm volatile("cp.async.wait_group 1;" ::: "memory")

__device__ __forceinline__ void ldsm4(uint32_t a, uint32_t& r0, uint32_t& r1,
                                      uint32_t& r2, uint32_t& r3) {
    asm volatile("ldmatrix.sync.aligned.m8n8.x4.shared.b16 {%0,%1,%2,%3}, [%4];"
                 : "=r"(r0), "=r"(r1), "=r"(r2), "=r"(r3) : "r"(a));
}
__device__ __forceinline__ void mma16816(float* d, const uint32_t* a, const uint32_t* b) {
    asm volatile("mma.sync.aligned.m16n8k16.row.col.f32.bf16.bf16.f32 "
                 "{%0,%1,%2,%3}, {%4,%5,%6,%7}, {%8,%9}, {%0,%1,%2,%3};"
                 : "+f"(d[0]), "+f"(d[1]), "+f"(d[2]), "+f"(d[3])
                 : "r"(a[0]), "r"(a[1]), "r"(a[2]), "r"(a[3]), "r"(b[0]), "r"(b[1]));
}
__device__ __forceinline__ void split2(float v, __nv_bfloat16& h, __nv_bfloat16& l) {
    h = __float2bfloat16(v);
    l = __float2bfloat16(v - __bfloat162float(h));
}
__device__ __forceinline__ uint32_t pack_bf2(float a, float b) {
    __nv_bfloat162 p = __halves2bfloat162(__float2bfloat16(a), __float2bfloat16(b));
    return *reinterpret_cast<uint32_t*>(&p);
}

// ---------------------------------------------------------------------------
// Pre-pass: split weights fp32 -> bf16 hi/lo
// ---------------------------------------------------------------------------
__global__ __launch_bounds__(256) void split_w_kernel(
    const float* __restrict__ in, __nv_bfloat16* __restrict__ hi,
    __nv_bfloat16* __restrict__ lo, int n)
{
    int i = blockIdx.x * 256 + threadIdx.x;
    if (i < n) { __nv_bfloat16 h, l; split2(in[i], h, l); hi[i] = h; lo[i] = l; }
}

// ---------------------------------------------------------------------------
// Pre-pass: x [B,C,N] -> Xb hi/lo (same layout) + XT hi/lo ([B,N,C])
// ---------------------------------------------------------------------------
__global__ __launch_bounds__(1024) void conv_x_kernel(
    const float* __restrict__ x,
    __nv_bfloat16* __restrict__ xbh, __nv_bfloat16* __restrict__ xbl,
    __nv_bfloat16* __restrict__ xth, __nv_bfloat16* __restrict__ xtl)
{
    __shared__ float T[32][33];
    const int n0 = blockIdx.x * 32, c0 = blockIdx.y * 32, b = blockIdx.z;
    const int tx = threadIdx.x, ty = threadIdx.y;

    size_t src = ((size_t)(b * CH + c0 + ty) << 10) + n0 + tx;
    float v = x[src];
    { __nv_bfloat16 h, l; split2(v, h, l); xbh[src] = h; xbl[src] = l; }
    T[ty][tx] = v;
    __syncthreads();
    float u = T[tx][ty];
    size_t dst = ((size_t)b * NTOK + n0 + ty) * CH + c0 + tx;
    { __nv_bfloat16 h, l; split2(u, h, l); xth[dst] = h; xtl[dst] = l; }
}

// ---------------------------------------------------------------------------
// Softmax rows (fp32 in) -> bf16 hi/lo probs out
// ---------------------------------------------------------------------------
__global__ __launch_bounds__(256) void softmax_split_kernel(
    const float* __restrict__ S, __nv_bfloat16* __restrict__ Ph, __nv_bfloat16* __restrict__ Pl)
{
    const float4* row = reinterpret_cast<const float4*>(S + (size_t)blockIdx.x * NTOK);
    const int t = threadIdx.x;
    const int wid = t >> 5, lane = t & 31;

    float4 v = row[t];
    float m = fmaxf(fmaxf(v.x, v.y), fmaxf(v.z, v.w));
#pragma unroll
    for (int o = 16; o > 0; o >>= 1) m = fmaxf(m, __shfl_xor_sync(0xffffffffu, m, o));

    __shared__ float sred[8];
    __shared__ float sbc;
    if (!lane) sred[wid] = m;
    __syncthreads();
    if (t == 0) {
        float mm = sred[0];
#pragma unroll
        for (int i = 1; i < 8; i++) mm = fmaxf(mm, sred[i]);
        sbc = mm;
    }
    __syncthreads();
    m = sbc;

    v.x = __expf(v.x - m); v.y = __expf(v.y - m);
    v.z = __expf(v.z - m); v.w = __expf(v.w - m);
    float s = v.x + v.y + v.z + v.w;
#pragma unroll
    for (int o = 16; o > 0; o >>= 1) s += __shfl_xor_sync(0xffffffffu, s, o);
    __syncthreads();
    if (!lane) sred[wid] = s;
    __syncthreads();
    if (t == 0) {
        float ss = 0.f;
#pragma unroll
        for (int i = 0; i < 8; i++) ss += sred[i];
        sbc = 1.0f / ss;
    }
    __syncthreads();
    float inv = sbc;
    float p[4] = {v.x * inv, v.y * inv, v.z * inv, v.w * inv};

    __nv_bfloat16 h[4], l[4];
#pragma unroll
    for (int i = 0; i < 4; i++) split2(p[i], h[i], l[i]);
    size_t base = (size_t)blockIdx.x * NTOK + t * 4;
    __nv_bfloat162 h01 = __halves2bfloat162(h[0], h[1]);
    __nv_bfloat162 h23 = __halves2bfloat162(h[2], h[3]);
    __nv_bfloat162 l01 = __halves2bfloat162(l[0], l[1]);
    __nv_bfloat162 l23 = __halves2bfloat162(l[2], l[3]);
    *reinterpret_cast<uint2*>(Ph + base) =
        make_uint2(*reinterpret_cast<uint32_t*>(&h01), *reinterpret_cast<uint32_t*>(&h23));
    *reinterpret_cast<uint2*>(Pl + base) =
        make_uint2(*reinterpret_cast<uint32_t*>(&l01), *reinterpret_cast<uint32_t*>(&l23));
}

// ---------------------------------------------------------------------------
// HMMA bf16x3 NT GEMM: D[i][j] = sum_k A[i,k]*B[j,k], A=Ah+Al, B=Bh+Bl.
// CTA 128x128, BK=32, 3-stage cp.async pipeline, mma.sync m16n8k16.
// 8 warps: warp grid 2(M) x 4(N), warp tile 64x32.
// SMEM stage: Ah @0, Al @8K, Bh @16K, Bl @24K  (each 128x32 bf16 = 8KB)
// Swizzle: phys(row,chunk16B) = row*64 + ((chunk ^ ((row>>1)&3))*16)
// MODE 0: store fp32*SCALE   MODE 1: store bf16 hi/lo
// MODE 2: +bias relu, bf16 hi/lo   MODE 3: +bias +resid, fp32 transposed [B,C,N]
// ---------------------------------------------------------------------------
#define STAGE_BYTES 32768
#define NSTAGE 3
#define SMEM_BYTES (NSTAGE * STAGE_BYTES)

template <int MODE>
__global__ void __launch_bounds__(256) gemm_hmma(
    const __nv_bfloat16* __restrict__ Ah, const __nv_bfloat16* __restrict__ Al,
    int lda, size_t sAz,
    const __nv_bfloat16* __restrict__ Bh, const __nv_bfloat16* __restrict__ Bl,
    int ldb, size_t sBz,
    int K,
    float* __restrict__ outF,
    __nv_bfloat16* __restrict__ outH, __nv_bfloat16* __restrict__ outL,
    int ldo, size_t sOz,
    const float* __restrict__ bias, const float* __restrict__ resid)
{
    extern __shared__ char smem[];
    const uint32_t sb = smem_u32(smem);

    const int tid  = threadIdx.x;
    const int lane = tid & 31;
    const int w    = tid >> 5;
    const int wm   = w & 1;        // 0..1 : 64-row slab
    const int wn   = w >> 1;       // 0..3 : 32-col slab
    const int i0 = blockIdx.x * 128;
    const int j0 = blockIdx.y * 128;
    const int z  = blockIdx.z;

    // ---- cp.async constants: thread -> (row rw, 16B-chunk ch) + row rw+64
    const int ch = tid & 3;
    const int rw = tid >> 2;                                  // 0..63
    const uint32_t s0 = (uint32_t)rw * 64u + (uint32_t)(((ch ^ ((rw >> 1) & 3)) << 4));
    const uint32_t s1 = s0 + 4096u;                           // row + 64 (same swizzle phase)

    const __nv_bfloat16* gAh0 = Ah + (size_t)z * sAz + (size_t)(i0 + rw) * lda + ch * 8;
    const __nv_bfloat16* gAh1 = gAh0 + (size_t)64 * lda;
    const __nv_bfloat16* gAl0 = Al + (size_t)z * sAz + (size_t)(i0 + rw) * lda + ch * 8;
    const __nv_bfloat16* gAl1 = gAl0 + (size_t)64 * lda;
    const __nv_bfloat16* gBh0 = Bh + (size_t)z * sBz + (size_t)(j0 + rw) * ldb + ch * 8;
    const __nv_bfloat16* gBh1 = gBh0 + (size_t)64 * ldb;
    const __nv_bfloat16* gBl0 = Bl + (size_t)z * sBz + (size_t)(j0 + rw) * ldb + ch * 8;
    const __nv_bfloat16* gBl1 = gBl0 + (size_t)64 * ldb;

    // ---- ldmatrix per-thread row/col geometry
    const int rA = wm * 64 + ((lane >> 3) & 1) * 8 + (lane & 7);   // A rows (per mi: +16)
    const int rB = wn * 32 + ((lane >> 4) << 3) + (lane & 7);      // B rows (per q: +16)
    const int swA = (rA >> 1) & 3;
    const int swB = (rB >> 1) & 3;
    const uint32_t rowA64 = (uint32_t)rA * 64u;
    const uint32_t rowB64 = (uint32_t)rB * 64u;

    float acc[64];
#pragma unroll
    for (int i = 0; i < 64; i++) acc[i] = 0.f;

    const int NC = K >> 5;    // BK=32

    // issue stage loads for chunk c into stage st
    auto issue = [&](int c, int st) {
        const uint32_t base = sb + (uint32_t)st * STAGE_BYTES;
        const int ko = c << 5;
        cpa16(base +          s0, gAh0 + ko);
        cpa16(base +          s1, gAh1 + ko);
        cpa16(base +  8192u + s0, gAl0 + ko);
        cpa16(base +  8192u + s1, gAl1 + ko);
        cpa16(base + 16384u + s0, gBh0 + ko);
        cpa16(base + 16384u + s1, gBh1 + ko);
        cpa16(base + 24576u + s0, gBl0 + ko);
        cpa16(base + 24576u + s1, gBl1 + ko);
    };

    issue(0, 0); CP_COMMIT();
    if (NC > 1) issue(1, 1);
    CP_COMMIT();

    for (int c = 0; c < NC; c++) {
        CP_WAIT1();
        __syncthreads();
        if (c + 2 < NC) issue(c + 2, (c + 2) % NSTAGE);
        CP_COMMIT();

        const uint32_t tb = sb + (uint32_t)(c % NSTAGE) * STAGE_BYTES;
#pragma unroll
        for (int ks = 0; ks < 2; ks++) {
            const int cA = ks * 2 + (lane >> 4);
            const int cB = ks * 2 + ((lane >> 3) & 1);
            const uint32_t offA = rowA64 + (uint32_t)(((cA ^ swA) << 4));
            const uint32_t offB = rowB64 + (uint32_t)(((cB ^ swB) << 4));
            const uint32_t aH = tb + offA;            // Ah
            const uint32_t aL = tb + 8192u + offA;    // Al
            const uint32_t bH = tb + 16384u + offB;   // Bh
            const uint32_t bL = tb + 24576u + offB;   // Bl

            uint32_t af[16], bf[8];
            // pass 1: Ah * Bh
#pragma unroll
            for (int mi = 0; mi < 4; mi++)
                ldsm4(aH + mi * 1024u, af[mi*4+0], af[mi*4+1], af[mi*4+2], af[mi*4+3]);
            ldsm4(bH,          bf[0], bf[1], bf[2], bf[3]);
            ldsm4(bH + 1024u,  bf[4], bf[5], bf[6], bf[7]);
#pragma unroll
            for (int mi = 0; mi < 4; mi++)
#pragma unroll
                for (int ni = 0; ni < 4; ni++)
                    mma16816(&acc[(mi*4+ni)*4], &af[mi*4], &bf[ni*2]);
            // pass 2: Ah * Bl (A frags already live)
            ldsm4(bL,          bf[0], bf[1], bf[2], bf[3]);
            ldsm4(bL + 1024u,  bf[4], bf[5], bf[6], bf[7]);
#pragma unroll
            for (int mi = 0; mi < 4; mi++)
#pragma unroll
                for (int ni = 0; ni < 4; ni++)
                    mma16816(&acc[(mi*4+ni)*4], &af[mi*4], &bf[ni*2]);
            // pass 3: Al * Bh
#pragma unroll
            for (int mi = 0; mi < 4; mi++)
                ldsm4(aL + mi * 1024u, af[mi*4+0], af[mi*4+1], af[mi*4+2], af[mi*4+3]);
            ldsm4(bH,          bf[0], bf[1], bf[2], bf[3]);
            ldsm4(bH + 1024u,  bf[4], bf[5], bf[6], bf[7]);
#pragma unroll
            for (int mi = 0; mi < 4; mi++)
#pragma unroll
                for (int ni = 0; ni < 4; ni++)
                    mma16816(&acc[(mi*4+ni)*4], &af[mi*4], &bf[ni*2]);
        }
    }

    // ------------------- epilogue (registers -> gmem) -------------------
#pragma unroll
    for (int mi = 0; mi < 4; mi++) {
        const int r0 = i0 + wm * 64 + mi * 16 + (lane >> 2);
        const int r1 = r0 + 8;
#pragma unroll
        for (int ni = 0; ni < 4; ni++) {
            const float* a = &acc[(mi*4+ni)*4];
            const int c0 = j0 + wn * 32 + ni * 8 + (lane & 3) * 2;

            if (MODE == 0) {
                float* C = outF + (size_t)z * sOz;
                *reinterpret_cast<float2*>(C + (size_t)r0 * ldo + c0) =
                    make_float2(a[0] * SCALE, a[1] * SCALE);
                *reinterpret_cast<float2*>(C + (size_t)r1 * ldo + c0) =
                    make_float2(a[2] * SCALE, a[3] * SCALE);
            } else if (MODE == 1 || MODE == 2) {
                float v0 = a[0], v1 = a[1], v2 = a[2], v3 = a[3];
                if (MODE == 2) {
                    float bj0 = __ldg(bias + c0), bj1 = __ldg(bias + c0 + 1);
                    v0 = fmaxf(v0 + bj0, 0.f); v1 = fmaxf(v1 + bj1, 0.f);
                    v2 = fmaxf(v2 + bj0, 0.f); v3 = fmaxf(v3 + bj1, 0.f);
                }
                const size_t o0 = (size_t)z * sOz + (size_t)r0 * ldo + c0;
                const size_t o1 = (size_t)z * sOz + (size_t)r1 * ldo + c0;
                __nv_bfloat16 h, l;
                __nv_bfloat16 h0, l0, h1, l1;
                split2(v0, h0, l0); split2(v1, h1, l1);
                {
                    __nv_bfloat162 hp = __halves2bfloat162(h0, h1);
                    __nv_bfloat162 lp = __halves2bfloat162(l0, l1);
                    *reinterpret_cast<uint32_t*>(outH + o0) = *reinterpret_cast<uint32_t*>(&hp);
                    *reinterpret_cast<uint32_t*>(outL + o0) = *reinterpret_cast<uint32_t*>(&lp);
                }
                split2(v2, h0, l0); split2(v3, h1, l1);
                {
                    __nv_bfloat162 hp = __halves2bfloat162(h0, h1);
                    __nv_bfloat162 lp = __halves2bfloat162(l0, l1);
                    *reinterpret_cast<uint32_t*>(outH + o1) = *reinterpret_cast<uint32_t*>(&hp);
                    *reinterpret_cast<uint32_t*>(outL + o1) = *reinterpret_cast<uint32_t*>(&lp);
                }
                (void)h; (void)l;
            } else {
                // MODE 3: out[b, c, n] = D + bias[c] + resid
                const int b  = r0 >> 10;
                const int n0 = r0 & (NTOK - 1);
                const int n1 = n0 + 8;
                const float bj0 = __ldg(bias + c0), bj1 = __ldg(bias + c0 + 1);
                const size_t base0 = ((size_t)(b * CH + c0) << 10);
                outF[base0 + n0]        = a[0] + bj0 + __ldg(resid + base0 + n0);
                outF[base0 + 1024 + n0] = a[1] + bj1 + __ldg(resid + base0 + 1024 + n0);
                outF[base0 + n1]        = a[2] + bj0 + __ldg(resid + base0 + n1);
                outF[base0 + 1024 + n1] = a[3] + bj1 + __ldg(resid + base0 + 1024 + n1);
            }
        }
    }
}

// ---------------------------------------------------------------------------
extern "C" void kernel_launch(void* const* d_in, const int* in_sizes, int n_in,
                              void* d_out, int out_size)
{
    const float* x  = (const float*)d_in[0];
    const float* w1 = (const float*)d_in[1];
    const float* b1 = (const float*)d_in[2];
    const float* w2 = (const float*)d_in[3];
    const float* b2 = (const float*)d_in[4];
    float* out = (float*)d_out;

    float *S;
    __nv_bfloat16 *Ph, *Pl, *XTh, *XTl, *Xbh, *Xbl, *Oh, *Ol, *Hh, *Hl;
    __nv_bfloat16 *w1h, *w1l, *w2h, *w2l;
    cudaGetSymbolAddress((void**)&S,   g_S);
    cudaGetSymbolAddress((void**)&Ph,  g_Ph);
    cudaGetSymbolAddress((void**)&Pl,  g_Pl);
    cudaGetSymbolAddress((void**)&XTh, g_XTh);
    cudaGetSymbolAddress((void**)&XTl, g_XTl);
    cudaGetSymbolAddress((void**)&Xbh, g_Xbh);
    cudaGetSymbolAddress((void**)&Xbl, g_Xbl);
    cudaGetSymbolAddress((void**)&Oh,  g_Oh);
    cudaGetSymbolAddress((void**)&Ol,  g_Ol);
    cudaGetSymbolAddress((void**)&Hh,  g_Hh);
    cudaGetSymbolAddress((void**)&Hl,  g_Hl);
    cudaGetSymbolAddress((void**)&w1h, g_w1h);
    cudaGetSymbolAddress((void**)&w1l, g_w1l);
    cudaGetSymbolAddress((void**)&w2h, g_w2h);
    cudaGetSymbolAddress((void**)&w2l, g_w2l);

    cudaFuncSetAttribute(gemm_hmma<0>, cudaFuncAttributeMaxDynamicSharedMemorySize, SMEM_BYTES);
    cudaFuncSetAttribute(gemm_hmma<1>, cudaFuncAttributeMaxDynamicSharedMemorySize, SMEM_BYTES);
    cudaFuncSetAttribute(gemm_hmma<2>, cudaFuncAttributeMaxDynamicSharedMemorySize, SMEM_BYTES);
    cudaFuncSetAttribute(gemm_hmma<3>, cudaFuncAttributeMaxDynamicSharedMemorySize, SMEM_BYTES);

    // pre-pass: split weights + x
    split_w_kernel<<<(HID * CH + 255) / 256, 256>>>(w1, w1h, w1l, HID * CH);
    split_w_kernel<<<(CH * HID + 255) / 256, 256>>>(w2, w2h, w2l, CH * HID);
    conv_x_kernel<<<dim3(NTOK / 32, CH / 32, BATCH), dim3(32, 32)>>>(x, Xbh, Xbl, XTh, XTl);

    // 1) S = SCALE * XT @ XT^T    [B, N, N]
    gemm_hmma<0><<<dim3(NTOK / 128, NTOK / 128, BATCH), 256, SMEM_BYTES>>>(
        XTh, XTl, CH, (size_t)NTOK * CH,
        XTh, XTl, CH, (size_t)NTOK * CH,
        CH, S, nullptr, nullptr, NTOK, (size_t)NTOK * NTOK, nullptr, nullptr);

    // 2) softmax + split
    softmax_split_kernel<<<BATCH * NTOK, 256>>>(S, Ph, Pl);

    // 3) O = P @ X^T              [B*N, C]
    gemm_hmma<1><<<dim3(NTOK / 128, CH / 128, BATCH), 256, SMEM_BYTES>>>(
        Ph, Pl, NTOK, (size_t)NTOK * NTOK,
        Xbh, Xbl, NTOK, (size_t)CH * NTOK,
        NTOK, nullptr, Oh, Ol, CH, (size_t)NTOK * CH, nullptr, nullptr);

    // 4) H = relu(O @ w1^T + b1)  [B*N, HID]
    gemm_hmma<2><<<dim3(BATCH * NTOK / 128, HID / 128, 1), 256, SMEM_BYTES>>>(
        Oh, Ol, CH, 0,
        w1h, w1l, CH, 0,
        CH, nullptr, Hh, Hl, HID, 0, b1, nullptr);

    // 5) y = H @ w2^T + b2 (+x), transposed store -> out [B, C, H, W]
    gemm_hmma<3><<<dim3(BATCH * NTOK / 128, CH / 128, 1), 256, SMEM_BYTES>>>(
        Hh, Hl, HID, 0,
        w2h, w2l, HID, 0,
        HID, out, nullptr, nullptr, CH, 0, b2, x);
}

// round 7
// speedup vs baseline: 4.4705x; 1.3542x over previous
#include <cuda_runtime.h>
#include <cuda_fp16.h>
#include <cstdint>

// Problem constants
#define BATCH 16
#define CH    512
#define NTOK  1024
#define HID   2048
#define SCALE 0.04419417382415922f   // 512^-0.5

// ---------------------------------------------------------------------------
// Static device scratch (fp16 operand copies; plain = hi copy for A-side)
// ---------------------------------------------------------------------------
__device__ float   g_S [(size_t)BATCH * NTOK * NTOK];   // fp32 scores
__device__ __half  g_Ph[(size_t)BATCH * NTOK * NTOK];   // probs (plain fp16)
__device__ __half  g_XTh[(size_t)BATCH * NTOK * CH];    // X^T [B,N,C] hi
__device__ __half  g_XTl[(size_t)BATCH * NTOK * CH];    //              lo
__device__ __half  g_Xbh[(size_t)BATCH * CH * NTOK];    // X   [B,C,N] hi
__device__ __half  g_Xbl[(size_t)BATCH * CH * NTOK];    //              lo
__device__ __half  g_Oh[(size_t)BATCH * NTOK * CH];     // attn out (plain)
__device__ __half  g_Hh[(size_t)BATCH * NTOK * HID];    // hidden (plain)
__device__ __half  g_w1h[(size_t)HID * CH];
__device__ __half  g_w1l[(size_t)HID * CH];
__device__ __half  g_w2h[(size_t)CH * HID];
__device__ __half  g_w2l[(size_t)CH * HID];

// ---------------------------------------------------------------------------
// Helpers (baseline PTX, valid at compute_103)
// ---------------------------------------------------------------------------
__device__ __forceinline__ uint32_t smem_u32(const void* p) {
    uint32_t a;
    asm("{ .reg .u64 t; cvta.to.shared.u64 t, %1; cvt.u32.u64 %0, t; }" : "=r"(a) : "l"(p));
    return a;
}
__device__ __forceinline__ void cpa16(uint32_t d, const void* s) {
    asm volatile("cp.async.cg.shared.global [%0], [%1], 16;" :: "r"(d), "l"(s));
}
#define CP_COMMIT() asm volatile("cp.async.commit_group;" ::: "memory")
#define CP_WAIT2()  asm volatile("cp.async.wait_group 2;" ::: "memory")

__device__ __forceinline__ void ldsm4(uint32_t a, uint32_t& r0, uint32_t& r1,
                                      uint32_t& r2, uint32_t& r3) {
    asm volatile("ldmatrix.sync.aligned.m8n8.x4.shared.b16 {%0,%1,%2,%3}, [%4];"
                 : "=r"(r0), "=r"(r1), "=r"(r2), "=r"(r3) : "r"(a));
}
__device__ __forceinline__ void mma16816(float* d, const uint32_t* a, const uint32_t* b) {
    asm volatile("mma.sync.aligned.m16n8k16.row.col.f32.f16.f16.f32 "
                 "{%0,%1,%2,%3}, {%4,%5,%6,%7}, {%8,%9}, {%0,%1,%2,%3};"
                 : "+f"(d[0]), "+f"(d[1]), "+f"(d[2]), "+f"(d[3])
                 : "r"(a[0]), "r"(a[1]), "r"(a[2]), "r"(a[3]), "r"(b[0]), "r"(b[1]));
}
__device__ __forceinline__ void split2h(float v, __half& h, __half& l) {
    h = __float2half_rn(v);
    l = __float2half_rn(v - __half2float(h));
}

// ---------------------------------------------------------------------------
// Pre-pass: split weights fp32 -> fp16 hi/lo
// ---------------------------------------------------------------------------
__global__ __launch_bounds__(256) void split_w_kernel(
    const float* __restrict__ in, __half* __restrict__ hi,
    __half* __restrict__ lo, int n)
{
    int i = blockIdx.x * 256 + threadIdx.x;
    if (i < n) { __half h, l; split2h(in[i], h, l); hi[i] = h; lo[i] = l; }
}

// ---------------------------------------------------------------------------
// Pre-pass: x [B,C,N] -> Xb hi/lo (same layout) + XT hi/lo ([B,N,C])
// ---------------------------------------------------------------------------
__global__ __launch_bounds__(1024) void conv_x_kernel(
    const float* __restrict__ x,
    __half* __restrict__ xbh, __half* __restrict__ xbl,
    __half* __restrict__ xth, __half* __restrict__ xtl)
{
    __shared__ float T[32][33];
    const int n0 = blockIdx.x * 32, c0 = blockIdx.y * 32, b = blockIdx.z;
    const int tx = threadIdx.x, ty = threadIdx.y;

    size_t src = ((size_t)(b * CH + c0 + ty) << 10) + n0 + tx;
    float v = x[src];
    { __half h, l; split2h(v, h, l); xbh[src] = h; xbl[src] = l; }
    T[ty][tx] = v;
    __syncthreads();
    float u = T[tx][ty];
    size_t dst = ((size_t)b * NTOK + n0 + ty) * CH + c0 + tx;
    { __half h, l; split2h(u, h, l); xth[dst] = h; xtl[dst] = l; }
}

// ---------------------------------------------------------------------------
// Softmax rows (fp32 in) -> plain fp16 probs out
// ---------------------------------------------------------------------------
__global__ __launch_bounds__(256) void softmax_h_kernel(
    const float* __restrict__ S, __half* __restrict__ Ph)
{
    const float4* row = reinterpret_cast<const float4*>(S + (size_t)blockIdx.x * NTOK);
    const int t = threadIdx.x;
    const int wid = t >> 5, lane = t & 31;

    float4 v = row[t];
    float m = fmaxf(fmaxf(v.x, v.y), fmaxf(v.z, v.w));
#pragma unroll
    for (int o = 16; o > 0; o >>= 1) m = fmaxf(m, __shfl_xor_sync(0xffffffffu, m, o));

    __shared__ float sred[8];
    __shared__ float sbc;
    if (!lane) sred[wid] = m;
    __syncthreads();
    if (t == 0) {
        float mm = sred[0];
#pragma unroll
        for (int i = 1; i < 8; i++) mm = fmaxf(mm, sred[i]);
        sbc = mm;
    }
    __syncthreads();
    m = sbc;

    v.x = __expf(v.x - m); v.y = __expf(v.y - m);
    v.z = __expf(v.z - m); v.w = __expf(v.w - m);
    float s = v.x + v.y + v.z + v.w;
#pragma unroll
    for (int o = 16; o > 0; o >>= 1) s += __shfl_xor_sync(0xffffffffu, s, o);
    __syncthreads();
    if (!lane) sred[wid] = s;
    __syncthreads();
    if (t == 0) {
        float ss = 0.f;
#pragma unroll
        for (int i = 0; i < 8; i++) ss += sred[i];
        sbc = 1.0f / ss;
    }
    __syncthreads();
    float inv = sbc;

    __half2 p01 = __floats2half2_rn(v.x * inv, v.y * inv);
    __half2 p23 = __floats2half2_rn(v.z * inv, v.w * inv);
    size_t base = (size_t)blockIdx.x * NTOK + t * 4;
    *reinterpret_cast<uint2*>(Ph + base) =
        make_uint2(*reinterpret_cast<uint32_t*>(&p01), *reinterpret_cast<uint32_t*>(&p23));
}

// ---------------------------------------------------------------------------
// HMMA fp16 2-pass NT GEMM: D[i][j] = sum_k A[i,k]*(Bh[j,k]+Bl[j,k])
// A plain fp16; B split hi/lo. CTA 128x128, BK=32, 4-stage cp.async,
// mma.sync m16n8k16.f32.f16. 8 warps 2(M)x4(N), warp tile 64x32.
// SMEM stage: A @0 (8KB), Bh @8K, Bl @16K  (each 128x32 fp16 = 8KB)
// Swizzle: phys(row,chunk16B) = row*64 + ((chunk ^ ((row>>1)&3))*16)
// MODE 0: store fp32*SCALE       MODE 1: store plain fp16
// MODE 2: +bias relu, fp16       MODE 3: +bias +resid, fp32 transposed [B,C,N]
// ---------------------------------------------------------------------------
#define STAGE_BYTES 24576
#define NSTAGE 4
#define SMEM_BYTES (NSTAGE * STAGE_BYTES)

template <int MODE>
__global__ void __launch_bounds__(256) gemm_hmma(
    const __half* __restrict__ A, int lda, size_t sAz,
    const __half* __restrict__ Bh, const __half* __restrict__ Bl,
    int ldb, size_t sBz,
    int K,
    float* __restrict__ outF, __half* __restrict__ outH,
    int ldo, size_t sOz,
    const float* __restrict__ bias, const float* __restrict__ resid)
{
    extern __shared__ char smem[];
    const uint32_t sb = smem_u32(smem);

    const int tid  = threadIdx.x;
    const int lane = tid & 31;
    const int w    = tid >> 5;
    const int wm   = w & 1;        // 0..1 : 64-row slab
    const int wn   = w >> 1;       // 0..3 : 32-col slab
    const int i0 = blockIdx.x * 128;
    const int j0 = blockIdx.y * 128;
    const int z  = blockIdx.z;

    // ---- cp.async mapping: thread -> (row rw, 16B chunk ch); rows rw and rw+64
    const int ch = tid & 3;
    const int rw = tid >> 2;                                  // 0..63
    const uint32_t s0 = (uint32_t)rw * 64u + (uint32_t)(((ch ^ ((rw >> 1) & 3)) << 4));
    const uint32_t s1 = s0 + 4096u;

    const __half* gA0  = A  + (size_t)z * sAz + (size_t)(i0 + rw) * lda + ch * 8;
    const __half* gA1  = gA0 + (size_t)64 * lda;
    const __half* gBh0 = Bh + (size_t)z * sBz + (size_t)(j0 + rw) * ldb + ch * 8;
    const __half* gBh1 = gBh0 + (size_t)64 * ldb;
    const __half* gBl0 = Bl + (size_t)z * sBz + (size_t)(j0 + rw) * ldb + ch * 8;
    const __half* gBl1 = gBl0 + (size_t)64 * ldb;

    // ---- ldmatrix geometry
    const int rA = wm * 64 + ((lane >> 3) & 1) * 8 + (lane & 7);
    const int rB = wn * 32 + ((lane >> 4) << 3) + (lane & 7);
    const int swA = (rA >> 1) & 3;
    const int swB = (rB >> 1) & 3;
    const uint32_t rowA64 = (uint32_t)rA * 64u;
    const uint32_t rowB64 = (uint32_t)rB * 64u;

    float acc[64];
#pragma unroll
    for (int i = 0; i < 64; i++) acc[i] = 0.f;

    const int NC = K >> 5;    // BK=32

    auto issue = [&](int c, int st) {
        const uint32_t base = sb + (uint32_t)st * STAGE_BYTES;
        const int ko = c << 5;
        cpa16(base +          s0, gA0  + ko);
        cpa16(base +          s1, gA1  + ko);
        cpa16(base +  8192u + s0, gBh0 + ko);
        cpa16(base +  8192u + s1, gBh1 + ko);
        cpa16(base + 16384u + s0, gBl0 + ko);
        cpa16(base + 16384u + s1, gBl1 + ko);
    };

    issue(0, 0); CP_COMMIT();
    issue(1, 1); CP_COMMIT();
    issue(2, 2); CP_COMMIT();

    for (int c = 0; c < NC; c++) {
        CP_WAIT2();
        __syncthreads();
        if (c + 3 < NC) issue(c + 3, (c + 3) & (NSTAGE - 1));
        CP_COMMIT();

        const uint32_t tb = sb + (uint32_t)(c & (NSTAGE - 1)) * STAGE_BYTES;
#pragma unroll
        for (int ks = 0; ks < 2; ks++) {
            const int cA = ks * 2 + (lane >> 4);
            const int cB = ks * 2 + ((lane >> 3) & 1);
            const uint32_t offA = rowA64 + (uint32_t)(((cA ^ swA) << 4));
            const uint32_t offB = rowB64 + (uint32_t)(((cB ^ swB) << 4));
            const uint32_t aA = tb + offA;
            const uint32_t bH = tb + 8192u + offB;
            const uint32_t bL = tb + 16384u + offB;

            uint32_t af[16], bh[8], bl[8];
#pragma unroll
            for (int mi = 0; mi < 4; mi++)
                ldsm4(aA + mi * 1024u, af[mi*4+0], af[mi*4+1], af[mi*4+2], af[mi*4+3]);
            ldsm4(bH,          bh[0], bh[1], bh[2], bh[3]);
            ldsm4(bH + 1024u,  bh[4], bh[5], bh[6], bh[7]);
            ldsm4(bL,          bl[0], bl[1], bl[2], bl[3]);
            ldsm4(bL + 1024u,  bl[4], bl[5], bl[6], bl[7]);
            // pass 1: A * Bh
#pragma unroll
            for (int mi = 0; mi < 4; mi++)
#pragma unroll
                for (int ni = 0; ni < 4; ni++)
                    mma16816(&acc[(mi*4+ni)*4], &af[mi*4], &bh[ni*2]);
            // pass 2: A * Bl
#pragma unroll
            for (int mi = 0; mi < 4; mi++)
#pragma unroll
                for (int ni = 0; ni < 4; ni++)
                    mma16816(&acc[(mi*4+ni)*4], &af[mi*4], &bl[ni*2]);
        }
    }

    // ------------------- epilogue (registers -> gmem) -------------------
#pragma unroll
    for (int mi = 0; mi < 4; mi++) {
        const int r0 = i0 + wm * 64 + mi * 16 + (lane >> 2);
        const int r1 = r0 + 8;
#pragma unroll
        for (int ni = 0; ni < 4; ni++) {
            const float* a = &acc[(mi*4+ni)*4];
            const int c0 = j0 + wn * 32 + ni * 8 + (lane & 3) * 2;

            if (MODE == 0) {
                float* C = outF + (size_t)z * sOz;
                *reinterpret_cast<float2*>(C + (size_t)r0 * ldo + c0) =
                    make_float2(a[0] * SCALE, a[1] * SCALE);
                *reinterpret_cast<float2*>(C + (size_t)r1 * ldo + c0) =
                    make_float2(a[2] * SCALE, a[3] * SCALE);
            } else if (MODE == 1 || MODE == 2) {
                float v0 = a[0], v1 = a[1], v2 = a[2], v3 = a[3];
                if (MODE == 2) {
                    float bj0 = __ldg(bias + c0), bj1 = __ldg(bias + c0 + 1);
                    v0 = fmaxf(v0 + bj0, 0.f); v1 = fmaxf(v1 + bj1, 0.f);
                    v2 = fmaxf(v2 + bj0, 0.f); v3 = fmaxf(v3 + bj1, 0.f);
                }
                const size_t o0 = (size_t)z * sOz + (size_t)r0 * ldo + c0;
                const size_t o1 = (size_t)z * sOz + (size_t)r1 * ldo + c0;
                __half2 p0 = __floats2half2_rn(v0, v1);
                __half2 p1 = __floats2half2_rn(v2, v3);
                *reinterpret_cast<uint32_t*>(outH + o0) = *reinterpret_cast<uint32_t*>(&p0);
                *reinterpret_cast<uint32_t*>(outH + o1) = *reinterpret_cast<uint32_t*>(&p1);
            } else {
                // MODE 3: out[b, c, n] = D + bias[c] + resid
                const int b  = r0 >> 10;
                const int n0 = r0 & (NTOK - 1);
                const int n1 = n0 + 8;
                const float bj0 = __ldg(bias + c0), bj1 = __ldg(bias + c0 + 1);
                const size_t base0 = ((size_t)(b * CH + c0) << 10);
                outF[base0 + n0]        = a[0] + bj0 + __ldg(resid + base0 + n0);
                outF[base0 + 1024 + n0] = a[1] + bj1 + __ldg(resid + base0 + 1024 + n0);
                outF[base0 + n1]        = a[2] + bj0 + __ldg(resid + base0 + n1);
                outF[base0 + 1024 + n1] = a[3] + bj1 + __ldg(resid + base0 + 1024 + n1);
            }
        }
    }
}

// ---------------------------------------------------------------------------
extern "C" void kernel_launch(void* const* d_in, const int* in_sizes, int n_in,
                              void* d_out, int out_size)
{
    const float* x  = (const float*)d_in[0];
    const float* w1 = (const float*)d_in[1];
    const float* b1 = (const float*)d_in[2];
    const float* w2 = (const float*)d_in[3];
    const float* b2 = (const float*)d_in[4];
    float* out = (float*)d_out;

    float *S;
    __half *Ph, *XTh, *XTl, *Xbh, *Xbl, *Oh, *Hh, *w1h, *w1l, *w2h, *w2l;
    cudaGetSymbolAddress((void**)&S,   g_S);
    cudaGetSymbolAddress((void**)&Ph,  g_Ph);
    cudaGetSymbolAddress((void**)&XTh, g_XTh);
    cudaGetSymbolAddress((void**)&XTl, g_XTl);
    cudaGetSymbolAddress((void**)&Xbh, g_Xbh);
    cudaGetSymbolAddress((void**)&Xbl, g_Xbl);
    cudaGetSymbolAddress((void**)&Oh,  g_Oh);
    cudaGetSymbolAddress((void**)&Hh,  g_Hh);
    cudaGetSymbolAddress((void**)&w1h, g_w1h);
    cudaGetSymbolAddress((void**)&w1l, g_w1l);
    cudaGetSymbolAddress((void**)&w2h, g_w2h);
    cudaGetSymbolAddress((void**)&w2l, g_w2l);

    cudaFuncSetAttribute(gemm_hmma<0>, cudaFuncAttributeMaxDynamicSharedMemorySize, SMEM_BYTES);
    cudaFuncSetAttribute(gemm_hmma<1>, cudaFuncAttributeMaxDynamicSharedMemorySize, SMEM_BYTES);
    cudaFuncSetAttribute(gemm_hmma<2>, cudaFuncAttributeMaxDynamicSharedMemorySize, SMEM_BYTES);
    cudaFuncSetAttribute(gemm_hmma<3>, cudaFuncAttributeMaxDynamicSharedMemorySize, SMEM_BYTES);

    // pre-pass: split weights + x
    split_w_kernel<<<(HID * CH + 255) / 256, 256>>>(w1, w1h, w1l, HID * CH);
    split_w_kernel<<<(CH * HID + 255) / 256, 256>>>(w2, w2h, w2l, CH * HID);
    conv_x_kernel<<<dim3(NTOK / 32, CH / 32, BATCH), dim3(32, 32)>>>(x, Xbh, Xbl, XTh, XTl);

    // 1) S = SCALE * XT @ XT^T    [B, N, N]   (A plain = XT hi; B split = XT hi/lo)
    gemm_hmma<0><<<dim3(NTOK / 128, NTOK / 128, BATCH), 256, SMEM_BYTES>>>(
        XTh, CH, (size_t)NTOK * CH,
        XTh, XTl, CH, (size_t)NTOK * CH,
        CH, S, nullptr, NTOK, (size_t)NTOK * NTOK, nullptr, nullptr);

    // 2) softmax -> plain fp16 probs
    softmax_h_kernel<<<BATCH * NTOK, 256>>>(S, Ph);

    // 3) O = P @ X^T              [B*N, C]   (A plain = P; B split = Xb hi/lo)
    gemm_hmma<1><<<dim3(NTOK / 128, CH / 128, BATCH), 256, SMEM_BYTES>>>(
        Ph, NTOK, (size_t)NTOK * NTOK,
        Xbh, Xbl, NTOK, (size_t)CH * NTOK,
        NTOK, nullptr, Oh, CH, (size_t)NTOK * CH, nullptr, nullptr);

    // 4) H = relu(O @ w1^T + b1)  [B*N, HID]  (A plain = O; B split = w1)
    gemm_hmma<2><<<dim3(BATCH * NTOK / 128, HID / 128, 1), 256, SMEM_BYTES>>>(
        Oh, CH, 0,
        w1h, w1l, CH, 0,
        CH, nullptr, Hh, HID, 0, b1, nullptr);

    // 5) y = H @ w2^T + b2 (+x), transposed store -> out [B, C, H, W]
    gemm_hmma<3><<<dim3(BATCH * NTOK / 128, CH / 128, 1), 256, SMEM_BYTES>>>(
        Hh, HID, 0,
        w2h, w2l, HID, 0,
        HID, out, nullptr, CH, 0, b2, x);
}

// round 8
// speedup vs baseline: 7.3700x; 1.6486x over previous
#include <cuda_runtime.h>
#include <cuda_fp16.h>
#include <cstdint>

// Problem constants
#define BATCH 16
#define CH    512
#define NTOK  1024
#define HID   2048
#define SCALE 0.04419417382415922f   // 512^-0.5

// ---------------------------------------------------------------------------
// Static device scratch (all operands plain fp16)
// ---------------------------------------------------------------------------
__device__ float   g_S [(size_t)BATCH * NTOK * NTOK];   // fp32 scores
__device__ __half  g_P [(size_t)BATCH * NTOK * NTOK];   // probs fp16
__device__ __half  g_XT[(size_t)BATCH * NTOK * CH];     // X^T [B,N,C]
__device__ __half  g_Xb[(size_t)BATCH * CH * NTOK];     // X   [B,C,N]
__device__ __half  g_O [(size_t)BATCH * NTOK * CH];     // attn out [B*N, C]
__device__ __half  g_H [(size_t)BATCH * NTOK * HID];    // hidden   [B*N, HID]
__device__ __half  g_w1[(size_t)HID * CH];
__device__ __half  g_w2[(size_t)CH * HID];

// ---------------------------------------------------------------------------
// Helpers (baseline PTX, valid at compute_103)
// ---------------------------------------------------------------------------
__device__ __forceinline__ uint32_t smem_u32(const void* p) {
    uint32_t a;
    asm("{ .reg .u64 t; cvta.to.shared.u64 t, %1; cvt.u32.u64 %0, t; }" : "=r"(a) : "l"(p));
    return a;
}
__device__ __forceinline__ void cpa16(uint32_t d, const void* s) {
    asm volatile("cp.async.cg.shared.global [%0], [%1], 16;" :: "r"(d), "l"(s));
}
#define CP_COMMIT() asm volatile("cp.async.commit_group;" ::: "memory")
#define CP_WAIT2()  asm volatile("cp.async.wait_group 2;" ::: "memory")

__device__ __forceinline__ void ldsm4(uint32_t a, uint32_t& r0, uint32_t& r1,
                                      uint32_t& r2, uint32_t& r3) {
    asm volatile("ldmatrix.sync.aligned.m8n8.x4.shared.b16 {%0,%1,%2,%3}, [%4];"
                 : "=r"(r0), "=r"(r1), "=r"(r2), "=r"(r3) : "r"(a));
}
__device__ __forceinline__ void mma16816(float* d, const uint32_t* a, const uint32_t* b) {
    asm volatile("mma.sync.aligned.m16n8k16.row.col.f32.f16.f16.f32 "
                 "{%0,%1,%2,%3}, {%4,%5,%6,%7}, {%8,%9}, {%0,%1,%2,%3};"
                 : "+f"(d[0]), "+f"(d[1]), "+f"(d[2]), "+f"(d[3])
                 : "r"(a[0]), "r"(a[1]), "r"(a[2]), "r"(a[3]), "r"(b[0]), "r"(b[1]));
}

// ---------------------------------------------------------------------------
// Pre-pass: convert weights fp32 -> fp16
// ---------------------------------------------------------------------------
__global__ __launch_bounds__(256) void cvt_w_kernel(
    const float* __restrict__ in, __half* __restrict__ out, int n)
{
    int i = blockIdx.x * 256 + threadIdx.x;
    if (i < n) out[i] = __float2half_rn(in[i]);
}

// ---------------------------------------------------------------------------
// Pre-pass: x [B,C,N] -> Xb fp16 (same layout) + XT fp16 ([B,N,C])
// ---------------------------------------------------------------------------
__global__ __launch_bounds__(1024) void conv_x_kernel(
    const float* __restrict__ x,
    __half* __restrict__ xb, __half* __restrict__ xt)
{
    __shared__ float T[32][33];
    const int n0 = blockIdx.x * 32, c0 = blockIdx.y * 32, b = blockIdx.z;
    const int tx = threadIdx.x, ty = threadIdx.y;

    size_t src = ((size_t)(b * CH + c0 + ty) << 10) + n0 + tx;
    float v = x[src];
    xb[src] = __float2half_rn(v);
    T[ty][tx] = v;
    __syncthreads();
    float u = T[tx][ty];
    size_t dst = ((size_t)b * NTOK + n0 + ty) * CH + c0 + tx;
    xt[dst] = __float2half_rn(u);
}

// ---------------------------------------------------------------------------
// Softmax rows (fp32 in) -> fp16 probs out
// ---------------------------------------------------------------------------
__global__ __launch_bounds__(256) void softmax_h_kernel(
    const float* __restrict__ S, __half* __restrict__ P)
{
    const float4* row = reinterpret_cast<const float4*>(S + (size_t)blockIdx.x * NTOK);
    const int t = threadIdx.x;
    const int wid = t >> 5, lane = t & 31;

    float4 v = row[t];
    float m = fmaxf(fmaxf(v.x, v.y), fmaxf(v.z, v.w));
#pragma unroll
    for (int o = 16; o > 0; o >>= 1) m = fmaxf(m, __shfl_xor_sync(0xffffffffu, m, o));

    __shared__ float sred[8];
    __shared__ float sbc;
    if (!lane) sred[wid] = m;
    __syncthreads();
    if (t == 0) {
        float mm = sred[0];
#pragma unroll
        for (int i = 1; i < 8; i++) mm = fmaxf(mm, sred[i]);
        sbc = mm;
    }
    __syncthreads();
    m = sbc;

    v.x = __expf(v.x - m); v.y = __expf(v.y - m);
    v.z = __expf(v.z - m); v.w = __expf(v.w - m);
    float s = v.x + v.y + v.z + v.w;
#pragma unroll
    for (int o = 16; o > 0; o >>= 1) s += __shfl_xor_sync(0xffffffffu, s, o);
    __syncthreads();
    if (!lane) sred[wid] = s;
    __syncthreads();
    if (t == 0) {
        float ss = 0.f;
#pragma unroll
        for (int i = 0; i < 8; i++) ss += sred[i];
        sbc = 1.0f / ss;
    }
    __syncthreads();
    float inv = sbc;

    __half2 p01 = __floats2half2_rn(v.x * inv, v.y * inv);
    __half2 p23 = __floats2half2_rn(v.z * inv, v.w * inv);
    size_t base = (size_t)blockIdx.x * NTOK + t * 4;
    *reinterpret_cast<uint2*>(P + base) =
        make_uint2(*reinterpret_cast<uint32_t*>(&p01), *reinterpret_cast<uint32_t*>(&p23));
}

// ---------------------------------------------------------------------------
// HMMA fp16 NT GEMM: D[i][j] = sum_k A[i,k]*B[j,k]
// CTA 128x128, BK=32, 4-stage cp.async, mma.sync m16n8k16.f32.f16.
// 8 warps 2(M)x4(N), warp tile 64x32.
// SMEM stage: A @0 (8KB), B @8K (8KB)   -> 16KB/stage
// Swizzle: phys(row,chunk16B) = row*64 + ((chunk ^ ((row>>1)&3))*16)
// MODE 0: store fp32*SCALE       MODE 1: store fp16
// MODE 2: +bias relu, fp16       MODE 3: +bias +resid, fp32 transposed [B,C,N]
// ---------------------------------------------------------------------------
#define STAGE_BYTES 16384
#define NSTAGE 4
#define SMEM_BYTES (NSTAGE * STAGE_BYTES)

template <int MODE>
__global__ void __launch_bounds__(256) gemm_hmma(
    const __half* __restrict__ A, int lda, size_t sAz,
    const __half* __restrict__ B, int ldb, size_t sBz,
    int K,
    float* __restrict__ outF, __half* __restrict__ outH,
    int ldo, size_t sOz,
    const float* __restrict__ bias, const float* __restrict__ resid)
{
    extern __shared__ char smem[];
    const uint32_t sb = smem_u32(smem);

    const int tid  = threadIdx.x;
    const int lane = tid & 31;
    const int w    = tid >> 5;
    const int wm   = w & 1;        // 0..1 : 64-row slab
    const int wn   = w >> 1;       // 0..3 : 32-col slab
    const int i0 = blockIdx.x * 128;
    const int j0 = blockIdx.y * 128;
    const int z  = blockIdx.z;

    // ---- cp.async mapping: thread -> (row rw, 16B chunk ch); rows rw and rw+64
    const int ch = tid & 3;
    const int rw = tid >> 2;                                  // 0..63
    const uint32_t s0 = (uint32_t)rw * 64u + (uint32_t)(((ch ^ ((rw >> 1) & 3)) << 4));
    const uint32_t s1 = s0 + 4096u;

    const __half* gA0 = A + (size_t)z * sAz + (size_t)(i0 + rw) * lda + ch * 8;
    const __half* gA1 = gA0 + (size_t)64 * lda;
    const __half* gB0 = B + (size_t)z * sBz + (size_t)(j0 + rw) * ldb + ch * 8;
    const __half* gB1 = gB0 + (size_t)64 * ldb;

    // ---- ldmatrix geometry
    const int rA = wm * 64 + ((lane >> 3) & 1) * 8 + (lane & 7);
    const int rB = wn * 32 + ((lane >> 4) << 3) + (lane & 7);
    const int swA = (rA >> 1) & 3;
    const int swB = (rB >> 1) & 3;
    const uint32_t rowA64 = (uint32_t)rA * 64u;
    const uint32_t rowB64 = (uint32_t)rB * 64u;

    float acc[64];
#pragma unroll
    for (int i = 0; i < 64; i++) acc[i] = 0.f;

    const int NC = K >> 5;    // BK=32

    auto issue = [&](int c, int st) {
        const uint32_t base = sb + (uint32_t)st * STAGE_BYTES;
        const int ko = c << 5;
        cpa16(base +         s0, gA0 + ko);
        cpa16(base +         s1, gA1 + ko);
        cpa16(base + 8192u + s0, gB0 + ko);
        cpa16(base + 8192u + s1, gB1 + ko);
    };

    issue(0, 0); CP_COMMIT();
    issue(1, 1); CP_COMMIT();
    issue(2, 2); CP_COMMIT();

    for (int c = 0; c < NC; c++) {
        CP_WAIT2();
        __syncthreads();
        if (c + 3 < NC) issue(c + 3, (c + 3) & (NSTAGE - 1));
        CP_COMMIT();

        const uint32_t tb = sb + (uint32_t)(c & (NSTAGE - 1)) * STAGE_BYTES;
#pragma unroll
        for (int ks = 0; ks < 2; ks++) {
            const int cA = ks * 2 + (lane >> 4);
            const int cB = ks * 2 + ((lane >> 3) & 1);
            const uint32_t offA = rowA64 + (uint32_t)(((cA ^ swA) << 4));
            const uint32_t offB = rowB64 + (uint32_t)(((cB ^ swB) << 4));
            const uint32_t aA = tb + offA;
            const uint32_t bB = tb + 8192u + offB;

            uint32_t af[16], bf[8];
#pragma unroll
            for (int mi = 0; mi < 4; mi++)
                ldsm4(aA + mi * 1024u, af[mi*4+0], af[mi*4+1], af[mi*4+2], af[mi*4+3]);
            ldsm4(bB,          bf[0], bf[1], bf[2], bf[3]);
            ldsm4(bB + 1024u,  bf[4], bf[5], bf[6], bf[7]);
#pragma unroll
            for (int mi = 0; mi < 4; mi++)
#pragma unroll
                for (int ni = 0; ni < 4; ni++)
                    mma16816(&acc[(mi*4+ni)*4], &af[mi*4], &bf[ni*2]);
        }
    }

    // ------------------- epilogue (registers -> gmem) -------------------
#pragma unroll
    for (int mi = 0; mi < 4; mi++) {
        const int r0 = i0 + wm * 64 + mi * 16 + (lane >> 2);
        const int r1 = r0 + 8;
#pragma unroll
        for (int ni = 0; ni < 4; ni++) {
            const float* a = &acc[(mi*4+ni)*4];
            const int c0 = j0 + wn * 32 + ni * 8 + (lane & 3) * 2;

            if (MODE == 0) {
                float* C = outF + (size_t)z * sOz;
                *reinterpret_cast<float2*>(C + (size_t)r0 * ldo + c0) =
                    make_float2(a[0] * SCALE, a[1] * SCALE);
                *reinterpret_cast<float2*>(C + (size_t)r1 * ldo + c0) =
                    make_float2(a[2] * SCALE, a[3] * SCALE);
            } else if (MODE == 1 || MODE == 2) {
                float v0 = a[0], v1 = a[1], v2 = a[2], v3 = a[3];
                if (MODE == 2) {
                    float bj0 = __ldg(bias + c0), bj1 = __ldg(bias + c0 + 1);
                    v0 = fmaxf(v0 + bj0, 0.f); v1 = fmaxf(v1 + bj1, 0.f);
                    v2 = fmaxf(v2 + bj0, 0.f); v3 = fmaxf(v3 + bj1, 0.f);
                }
                const size_t o0 = (size_t)z * sOz + (size_t)r0 * ldo + c0;
                const size_t o1 = (size_t)z * sOz + (size_t)r1 * ldo + c0;
                __half2 p0 = __floats2half2_rn(v0, v1);
                __half2 p1 = __floats2half2_rn(v2, v3);
                *reinterpret_cast<uint32_t*>(outH + o0) = *reinterpret_cast<uint32_t*>(&p0);
                *reinterpret_cast<uint32_t*>(outH + o1) = *reinterpret_cast<uint32_t*>(&p1);
            } else {
                // MODE 3: out[b, c, n] = D + bias[c] + resid
                const int b  = r0 >> 10;
                const int n0 = r0 & (NTOK - 1);
                const int n1 = n0 + 8;
                const float bj0 = __ldg(bias + c0), bj1 = __ldg(bias + c0 + 1);
                const size_t base0 = ((size_t)(b * CH + c0) << 10);
                outF[base0 + n0]        = a[0] + bj0 + __ldg(resid + base0 + n0);
                outF[base0 + 1024 + n0] = a[1] + bj1 + __ldg(resid + base0 + 1024 + n0);
                outF[base0 + n1]        = a[2] + bj0 + __ldg(resid + base0 + n1);
                outF[base0 + 1024 + n1] = a[3] + bj1 + __ldg(resid + base0 + 1024 + n1);
            }
        }
    }
}

// ---------------------------------------------------------------------------
extern "C" void kernel_launch(void* const* d_in, const int* in_sizes, int n_in,
                              void* d_out, int out_size)
{
    const float* x  = (const float*)d_in[0];
    const float* w1 = (const float*)d_in[1];
    const float* b1 = (const float*)d_in[2];
    const float* w2 = (const float*)d_in[3];
    const float* b2 = (const float*)d_in[4];
    float* out = (float*)d_out;

    float *S;
    __half *P, *XT, *Xb, *O, *H, *w1h, *w2h;
    cudaGetSymbolAddress((void**)&S,   g_S);
    cudaGetSymbolAddress((void**)&P,   g_P);
    cudaGetSymbolAddress((void**)&XT,  g_XT);
    cudaGetSymbolAddress((void**)&Xb,  g_Xb);
    cudaGetSymbolAddress((void**)&O,   g_O);
    cudaGetSymbolAddress((void**)&H,   g_H);
    cudaGetSymbolAddress((void**)&w1h, g_w1);
    cudaGetSymbolAddress((void**)&w2h, g_w2);

    cudaFuncSetAttribute(gemm_hmma<0>, cudaFuncAttributeMaxDynamicSharedMemorySize, SMEM_BYTES);
    cudaFuncSetAttribute(gemm_hmma<1>, cudaFuncAttributeMaxDynamicSharedMemorySize, SMEM_BYTES);
    cudaFuncSetAttribute(gemm_hmma<2>, cudaFuncAttributeMaxDynamicSharedMemorySize, SMEM_BYTES);
    cudaFuncSetAttribute(gemm_hmma<3>, cudaFuncAttributeMaxDynamicSharedMemorySize, SMEM_BYTES);

    // pre-pass: convert weights + x to fp16
    cvt_w_kernel<<<(HID * CH + 255) / 256, 256>>>(w1, w1h, HID * CH);
    cvt_w_kernel<<<(CH * HID + 255) / 256, 256>>>(w2, w2h, CH * HID);
    conv_x_kernel<<<dim3(NTOK / 32, CH / 32, BATCH), dim3(32, 32)>>>(x, Xb, XT);

    // 1) S = SCALE * XT @ XT^T    [B, N, N]
    gemm_hmma<0><<<dim3(NTOK / 128, NTOK / 128, BATCH), 256, SMEM_BYTES>>>(
        XT, CH, (size_t)NTOK * CH,
        XT, CH, (size_t)NTOK * CH,
        CH, S, nullptr, NTOK, (size_t)NTOK * NTOK, nullptr, nullptr);

    // 2) softmax -> fp16 probs
    softmax_h_kernel<<<BATCH * NTOK, 256>>>(S, P);

    // 3) O = P @ X^T              [B*N, C]
    gemm_hmma<1><<<dim3(NTOK / 128, CH / 128, BATCH), 256, SMEM_BYTES>>>(
        P, NTOK, (size_t)NTOK * NTOK,
        Xb, NTOK, (size_t)CH * NTOK,
        NTOK, nullptr, O, CH, (size_t)NTOK * CH, nullptr, nullptr);

    // 4) H = relu(O @ w1^T + b1)  [B*N, HID]
    gemm_hmma<2><<<dim3(BATCH * NTOK / 128, HID / 128, 1), 256, SMEM_BYTES>>>(
        O, CH, 0,
        w1h, CH, 0,
        CH, nullptr, H, HID, 0, b1, nullptr);

    // 5) y = H @ w2^T + b2 (+x), transposed store -> out [B, C, H, W]
    gemm_hmma<3><<<dim3(BATCH * NTOK / 128, CH / 128, 1), 256, SMEM_BYTES>>>(
        H, HID, 0,
        w2h, HID, 0,
        HID, out, nullptr, CH, 0, b2, x);
}

// round 10
// speedup vs baseline: 8.2461x; 1.1189x over previous
#include <cuda_runtime.h>
#include <cuda_fp16.h>
#include <cstdint>

// Problem constants
#define BATCH 16
#define CH    512
#define NTOK  1024
#define HID   2048
#define SCALE 0.04419417382415922f   // 512^-0.5

// ---------------------------------------------------------------------------
// Static device scratch (all operands plain fp16)
// ---------------------------------------------------------------------------
__device__ float   g_S [(size_t)BATCH * NTOK * NTOK];   // fp32 scores
__device__ __half  g_P [(size_t)BATCH * NTOK * NTOK];   // probs fp16
__device__ __half  g_XT[(size_t)BATCH * NTOK * CH];     // X^T [B,N,C]
__device__ __half  g_Xb[(size_t)BATCH * CH * NTOK];     // X   [B,C,N]
__device__ __half  g_O [(size_t)BATCH * NTOK * CH];     // attn out [B*N, C]
__device__ __half  g_H [(size_t)BATCH * NTOK * HID];    // hidden   [B*N, HID]
__device__ __half  g_w1[(size_t)HID * CH];
__device__ __half  g_w2[(size_t)CH * HID];

// ---------------------------------------------------------------------------
// Helpers (baseline PTX, valid at compute_103)
// ---------------------------------------------------------------------------
__device__ __forceinline__ uint32_t smem_u32(const void* p) {
    uint32_t a;
    asm("{ .reg .u64 t; cvta.to.shared.u64 t, %1; cvt.u32.u64 %0, t; }" : "=r"(a) : "l"(p));
    return a;
}
__device__ __forceinline__ void cpa16(uint32_t d, const void* s) {
    asm volatile("cp.async.cg.shared.global [%0], [%1], 16;" :: "r"(d), "l"(s));
}
#define CP_COMMIT() asm volatile("cp.async.commit_group;" ::: "memory")
#define CP_WAIT1()  asm volatile("cp.async.wait_group 1;" ::: "memory")

__device__ __forceinline__ void ldsm4(uint32_t a, uint32_t& r0, uint32_t& r1,
                                      uint32_t& r2, uint32_t& r3) {
    asm volatile("ldmatrix.sync.aligned.m8n8.x4.shared.b16 {%0,%1,%2,%3}, [%4];"
                 : "=r"(r0), "=r"(r1), "=r"(r2), "=r"(r3) : "r"(a));
}
__device__ __forceinline__ void mma16816(float* d, const uint32_t* a, const uint32_t* b) {
    asm volatile("mma.sync.aligned.m16n8k16.row.col.f32.f16.f16.f32 "
                 "{%0,%1,%2,%3}, {%4,%5,%6,%7}, {%8,%9}, {%0,%1,%2,%3};"
                 : "+f"(d[0]), "+f"(d[1]), "+f"(d[2]), "+f"(d[3])
                 : "r"(a[0]), "r"(a[1]), "r"(a[2]), "r"(a[3]), "r"(b[0]), "r"(b[1]));
}

// ---------------------------------------------------------------------------
// Pre-pass: convert weights fp32 -> fp16
// ---------------------------------------------------------------------------
__global__ __launch_bounds__(256) void cvt_w_kernel(
    const float* __restrict__ in, __half* __restrict__ out, int n)
{
    int i = blockIdx.x * 256 + threadIdx.x;
    if (i < n) out[i] = __float2half_rn(in[i]);
}

// ---------------------------------------------------------------------------
// Pre-pass: x [B,C,N] -> Xb fp16 (same layout) + XT fp16 ([B,N,C])
// ---------------------------------------------------------------------------
__global__ __launch_bounds__(1024) void conv_x_kernel(
    const float* __restrict__ x,
    __half* __restrict__ xb, __half* __restrict__ xt)
{
    __shared__ float T[32][33];
    const int n0 = blockIdx.x * 32, c0 = blockIdx.y * 32, b = blockIdx.z;
    const int tx = threadIdx.x, ty = threadIdx.y;

    size_t src = ((size_t)(b * CH + c0 + ty) << 10) + n0 + tx;
    float v = x[src];
    xb[src] = __float2half_rn(v);
    T[ty][tx] = v;
    __syncthreads();
    float u = T[tx][ty];
    size_t dst = ((size_t)b * NTOK + n0 + ty) * CH + c0 + tx;
    xt[dst] = __float2half_rn(u);
}

// ---------------------------------------------------------------------------
// Softmax rows (fp32 in) -> fp16 probs out
// ---------------------------------------------------------------------------
__global__ __launch_bounds__(256) void softmax_h_kernel(
    const float* __restrict__ S, __half* __restrict__ P)
{
    const float4* row = reinterpret_cast<const float4*>(S + (size_t)blockIdx.x * NTOK);
    const int t = threadIdx.x;
    const int wid = t >> 5, lane = t & 31;

    float4 v = row[t];
    float m = fmaxf(fmaxf(v.x, v.y), fmaxf(v.z, v.w));
#pragma unroll
    for (int o = 16; o > 0; o >>= 1) m = fmaxf(m, __shfl_xor_sync(0xffffffffu, m, o));

    __shared__ float sred[8];
    __shared__ float sbc;
    if (!lane) sred[wid] = m;
    __syncthreads();
    if (t == 0) {
        float mm = sred[0];
#pragma unroll
        for (int i = 1; i < 8; i++) mm = fmaxf(mm, sred[i]);
        sbc = mm;
    }
    __syncthreads();
    m = sbc;

    v.x = __expf(v.x - m); v.y = __expf(v.y - m);
    v.z = __expf(v.z - m); v.w = __expf(v.w - m);
    float s = v.x + v.y + v.z + v.w;
#pragma unroll
    for (int o = 16; o > 0; o >>= 1) s += __shfl_xor_sync(0xffffffffu, s, o);
    __syncthreads();
    if (!lane) sred[wid] = s;
    __syncthreads();
    if (t == 0) {
        float ss = 0.f;
#pragma unroll
        for (int i = 0; i < 8; i++) ss += sred[i];
        sbc = 1.0f / ss;
    }
    __syncthreads();
    float inv = sbc;

    __half2 p01 = __floats2half2_rn(v.x * inv, v.y * inv);
    __half2 p23 = __floats2half2_rn(v.z * inv, v.w * inv);
    size_t base = (size_t)blockIdx.x * NTOK + t * 4;
    *reinterpret_cast<uint2*>(P + base) =
        make_uint2(*reinterpret_cast<uint32_t*>(&p01), *reinterpret_cast<uint32_t*>(&p23));
}

// ---------------------------------------------------------------------------
// HMMA fp16 NT GEMM: D[i][j] = sum_k A[i,k]*B[j,k]
// CTA 128x128, 4 warps (2x2), warp tile 64x64, BK=64, 3-stage cp.async ring.
// SMEM stage: A @0 (16KB), B @16K (16KB) -> 32KB/stage, rows 128B wide.
// Swizzle: phys(row,chunk16B) = row*128 + ((chunk ^ (row&7))*16)
// Per k16 step: 4 ldsm4 (A) + 4 ldsm4 (B) -> 32 MMAs  (1:4 ratio)
// MODE 0: store fp32*SCALE       MODE 1: store fp16
// MODE 2: +bias relu, fp16       MODE 3: +bias +resid, fp32 transposed [B,C,N]
// ---------------------------------------------------------------------------
#define STAGE_BYTES 32768
#define NSTAGE 3
#define SMEM_BYTES (NSTAGE * STAGE_BYTES)

template <int MODE>
__global__ void __launch_bounds__(128, 1) gemm_hmma(
    const __half* __restrict__ A, int lda, size_t sAz,
    const __half* __restrict__ B, int ldb, size_t sBz,
    int K,
    float* __restrict__ outF, __half* __restrict__ outH,
    int ldo, size_t sOz,
    const float* __restrict__ bias, const float* __restrict__ resid)
{
    extern __shared__ char smem[];
    const uint32_t sb = smem_u32(smem);

    const int tid  = threadIdx.x;
    const int lane = tid & 31;
    const int w    = tid >> 5;     // 0..3
    const int wm   = w & 1;        // 0..1 : 64-row slab
    const int wn   = w >> 1;       // 0..1 : 64-col slab
    const int i0 = blockIdx.x * 128;
    const int j0 = blockIdx.y * 128;
    const int z  = blockIdx.z;

    // ---- cp.async mapping: thread -> (row rw 0..15, 16B chunk ch 0..7)
    const int ch = tid & 7;
    const int rw = tid >> 3;                                  // 0..15
    const uint32_t sbase = (uint32_t)rw * 128u + (uint32_t)((ch ^ (rw & 7)) << 4);

    const __half* gA = A + (size_t)z * sAz + (size_t)(i0 + rw) * lda + ch * 8;
    const __half* gB = B + (size_t)z * sBz + (size_t)(j0 + rw) * ldb + ch * 8;

    // ---- ldmatrix geometry (within 64x64 warp tile)
    const int rA = wm * 64 + ((lane >> 3) & 1) * 8 + (lane & 7);   // A row (+16 per mi)
    const int rB = wn * 64 + ((lane >> 4) << 3) + (lane & 7);      // B row (+16 per pair)
    const int swA = rA & 7;
    const int swB = rB & 7;
    const uint32_t rowA = (uint32_t)rA * 128u;
    const uint32_t rowB = (uint32_t)rB * 128u;

    float acc[128];
#pragma unroll
    for (int i = 0; i < 128; i++) acc[i] = 0.f;

    const int NC = K >> 6;    // BK=64

    // issue one BK=64 stage: A(16KB)+B(16KB); each thread 8+8 cp.async of 16B
    auto issue = [&](int c, int st) {
        const uint32_t base = sb + (uint32_t)st * STAGE_BYTES;
        const int ko = c << 6;
#pragma unroll
        for (int it = 0; it < 8; it++)
            cpa16(base + sbase + it * 2048u, gA + ko + (size_t)(it * 16) * lda);
#pragma unroll
        for (int it = 0; it < 8; it++)
            cpa16(base + 16384u + sbase + it * 2048u, gB + ko + (size_t)(it * 16) * ldb);
    };

    issue(0, 0); CP_COMMIT();
    issue(1, 1); CP_COMMIT();

    int st_use = 0, st_pf = 2;
    for (int c = 0; c < NC; c++) {
        CP_WAIT1();
        __syncthreads();
        if (c + 2 < NC) issue(c + 2, st_pf);
        CP_COMMIT();

        const uint32_t tb = sb + (uint32_t)st_use * STAGE_BYTES;
#pragma unroll
        for (int ks = 0; ks < 4; ks++) {
            const int cA = ks * 2 + (lane >> 4);
            const int cB = ks * 2 + ((lane >> 3) & 1);
            const uint32_t aA = tb + rowA + (uint32_t)(((cA ^ swA) << 4));
            const uint32_t bB = tb + 16384u + rowB + (uint32_t)(((cB ^ swB) << 4));

            uint32_t af[16], bf[16];
#pragma unroll
            for (int mi = 0; mi < 4; mi++)
                ldsm4(aA + mi * 2048u, af[mi*4+0], af[mi*4+1], af[mi*4+2], af[mi*4+3]);
#pragma unroll
            for (int t = 0; t < 4; t++)
                ldsm4(bB + t * 2048u, bf[t*4+0], bf[t*4+1], bf[t*4+2], bf[t*4+3]);
#pragma unroll
            for (int mi = 0; mi < 4; mi++)
#pragma unroll
                for (int ni = 0; ni < 8; ni++)
                    mma16816(&acc[(mi*8+ni)*4], &af[mi*4], &bf[ni*2]);
        }
        st_use = (st_use == NSTAGE - 1) ? 0 : st_use + 1;
        st_pf  = (st_pf  == NSTAGE - 1) ? 0 : st_pf  + 1;
    }

    // ------------------- epilogue (registers -> gmem) -------------------
#pragma unroll
    for (int mi = 0; mi < 4; mi++) {
        const int r0 = i0 + wm * 64 + mi * 16 + (lane >> 2);
        const int r1 = r0 + 8;
#pragma unroll
        for (int ni = 0; ni < 8; ni++) {
            const float* a = &acc[(mi*8+ni)*4];
            const int c0 = j0 + wn * 64 + ni * 8 + (lane & 3) * 2;

            if (MODE == 0) {
                float* C = outF + (size_t)z * sOz;
                *reinterpret_cast<float2*>(C + (size_t)r0 * ldo + c0) =
                    make_float2(a[0] * SCALE, a[1] * SCALE);
                *reinterpret_cast<float2*>(C + (size_t)r1 * ldo + c0) =
                    make_float2(a[2] * SCALE, a[3] * SCALE);
            } else if (MODE == 1 || MODE == 2) {
                float v0 = a[0], v1 = a[1], v2 = a[2], v3 = a[3];
                if (MODE == 2) {
                    float bj0 = __ldg(bias + c0), bj1 = __ldg(bias + c0 + 1);
                    v0 = fmaxf(v0 + bj0, 0.f); v1 = fmaxf(v1 + bj1, 0.f);
                    v2 = fmaxf(v2 + bj0, 0.f); v3 = fmaxf(v3 + bj1, 0.f);
                }
                const size_t o0 = (size_t)z * sOz + (size_t)r0 * ldo + c0;
                const size_t o1 = (size_t)z * sOz + (size_t)r1 * ldo + c0;
                __half2 p0 = __floats2half2_rn(v0, v1);
                __half2 p1 = __floats2half2_rn(v2, v3);
                *reinterpret_cast<uint32_t*>(outH + o0) = *reinterpret_cast<uint32_t*>(&p0);
                *reinterpret_cast<uint32_t*>(outH + o1) = *reinterpret_cast<uint32_t*>(&p1);
            } else {
                // MODE 3: out[b, c, n] = D + bias[c] + resid
                const int b  = r0 >> 10;
                const int n0 = r0 & (NTOK - 1);
                const int n1 = n0 + 8;
                const float bj0 = __ldg(bias + c0), bj1 = __ldg(bias + c0 + 1);
                const size_t base0 = ((size_t)(b * CH + c0) << 10);
                outF[base0 + n0]        = a[0] + bj0 + __ldg(resid + base0 + n0);
                outF[base0 + 1024 + n0] = a[1] + bj1 + __ldg(resid + base0 + 1024 + n0);
                outF[base0 + n1]        = a[2] + bj0 + __ldg(resid + base0 + n1);
                outF[base0 + 1024 + n1] = a[3] + bj1 + __ldg(resid + base0 + 1024 + n1);
            }
        }
    }
}

// ---------------------------------------------------------------------------
extern "C" void kernel_launch(void* const* d_in, const int* in_sizes, int n_in,
                              void* d_out, int out_size)
{
    const float* x  = (const float*)d_in[0];
    const float* w1 = (const float*)d_in[1];
    const float* b1 = (const float*)d_in[2];
    const float* w2 = (const float*)d_in[3];
    const float* b2 = (const float*)d_in[4];
    float* out = (float*)d_out;

    float *S;
    __half *P, *XT, *Xb, *O, *H, *w1h, *w2h;
    cudaGetSymbolAddress((void**)&S,   g_S);
    cudaGetSymbolAddress((void**)&P,   g_P);
    cudaGetSymbolAddress((void**)&XT,  g_XT);
    cudaGetSymbolAddress((void**)&Xb,  g_Xb);
    cudaGetSymbolAddress((void**)&O,   g_O);
    cudaGetSymbolAddress((void**)&H,   g_H);
    cudaGetSymbolAddress((void**)&w1h, g_w1);
    cudaGetSymbolAddress((void**)&w2h, g_w2);

    cudaFuncSetAttribute(gemm_hmma<0>, cudaFuncAttributeMaxDynamicSharedMemorySize, SMEM_BYTES);
    cudaFuncSetAttribute(gemm_hmma<1>, cudaFuncAttributeMaxDynamicSharedMemorySize, SMEM_BYTES);
    cudaFuncSetAttribute(gemm_hmma<2>, cudaFuncAttributeMaxDynamicSharedMemorySize, SMEM_BYTES);
    cudaFuncSetAttribute(gemm_hmma<3>, cudaFuncAttributeMaxDynamicSharedMemorySize, SMEM_BYTES);

    // pre-pass: convert weights + x to fp16
    cvt_w_kernel<<<(HID * CH + 255) / 256, 256>>>(w1, w1h, HID * CH);
    cvt_w_kernel<<<(CH * HID + 255) / 256, 256>>>(w2, w2h, CH * HID);
    conv_x_kernel<<<dim3(NTOK / 32, CH / 32, BATCH), dim3(32, 32)>>>(x, Xb, XT);

    // 1) S = SCALE * XT @ XT^T    [B, N, N]
    gemm_hmma<0><<<dim3(NTOK / 128, NTOK / 128, BATCH), 128, SMEM_BYTES>>>(
        XT, CH, (size_t)NTOK * CH,
        XT, CH, (size_t)NTOK * CH,
        CH, S, nullptr, NTOK, (size_t)NTOK * NTOK, nullptr, nullptr);

    // 2) softmax -> fp16 probs
    softmax_h_kernel<<<BATCH * NTOK, 256>>>(S, P);

    // 3) O = P @ X^T              [B*N, C]
    gemm_hmma<1><<<dim3(NTOK / 128, CH / 128, BATCH), 128, SMEM_BYTES>>>(
        P, NTOK, (size_t)NTOK * NTOK,
        Xb, NTOK, (size_t)CH * NTOK,
        NTOK, nullptr, O, CH, (size_t)NTOK * CH, nullptr, nullptr);

    // 4) H = relu(O @ w1^T + b1)  [B*N, HID]
    gemm_hmma<2><<<dim3(BATCH * NTOK / 128, HID / 128, 1), 128, SMEM_BYTES>>>(
        O, CH, 0,
        w1h, CH, 0,
        CH, nullptr, H, HID, 0, b1, nullptr);

    // 5) y = H @ w2^T + b2 (+x), transposed store -> out [B, C, H, W]
    gemm_hmma<3><<<dim3(BATCH * NTOK / 128, CH / 128, 1), 128, SMEM_BYTES>>>(
        H, HID, 0,
        w2h, HID, 0,
        HID, out, nullptr, CH, 0, b2, x);
}

// round 11
// speedup vs baseline: 8.5919x; 1.0419x over previous
#include <cuda_runtime.h>
#include <cuda_fp16.h>
#include <cstdint>

// Problem constants
#define BATCH 16
#define CH    512
#define NTOK  1024
#define HID   2048
#define SCALE 0.04419417382415922f   // 512^-0.5

// ---------------------------------------------------------------------------
// Static device scratch (all operands plain fp16)
// ---------------------------------------------------------------------------
__device__ float   g_S [(size_t)BATCH * NTOK * NTOK];   // fp32 scores
__device__ __half  g_P [(size_t)BATCH * NTOK * NTOK];   // probs fp16
__device__ __half  g_XT[(size_t)BATCH * NTOK * CH];     // X^T [B,N,C]
__device__ __half  g_Xb[(size_t)BATCH * CH * NTOK];     // X   [B,C,N]
__device__ __half  g_O [(size_t)BATCH * NTOK * CH];     // attn out [B*N, C]
__device__ __half  g_H [(size_t)BATCH * NTOK * HID];    // hidden   [B*N, HID]
__device__ __half  g_w1[(size_t)HID * CH];
__device__ __half  g_w2[(size_t)CH * HID];

// ---------------------------------------------------------------------------
// Helpers (baseline PTX, valid at compute_103)
// ---------------------------------------------------------------------------
__device__ __forceinline__ uint32_t smem_u32(const void* p) {
    uint32_t a;
    asm("{ .reg .u64 t; cvta.to.shared.u64 t, %1; cvt.u32.u64 %0, t; }" : "=r"(a) : "l"(p));
    return a;
}
__device__ __forceinline__ void cpa16(uint32_t d, const void* s) {
    asm volatile("cp.async.cg.shared.global [%0], [%1], 16;" :: "r"(d), "l"(s));
}
#define CP_COMMIT() asm volatile("cp.async.commit_group;" ::: "memory")
#define CP_WAIT1()  asm volatile("cp.async.wait_group 1;" ::: "memory")

__device__ __forceinline__ void ldsm4(uint32_t a, uint32_t& r0, uint32_t& r1,
                                      uint32_t& r2, uint32_t& r3) {
    asm volatile("ldmatrix.sync.aligned.m8n8.x4.shared.b16 {%0,%1,%2,%3}, [%4];"
                 : "=r"(r0), "=r"(r1), "=r"(r2), "=r"(r3) : "r"(a));
}
__device__ __forceinline__ void mma16816(float* d, const uint32_t* a, const uint32_t* b) {
    asm volatile("mma.sync.aligned.m16n8k16.row.col.f32.f16.f16.f32 "
                 "{%0,%1,%2,%3}, {%4,%5,%6,%7}, {%8,%9}, {%0,%1,%2,%3};"
                 : "+f"(d[0]), "+f"(d[1]), "+f"(d[2]), "+f"(d[3])
                 : "r"(a[0]), "r"(a[1]), "r"(a[2]), "r"(a[3]), "r"(b[0]), "r"(b[1]));
}

// ---------------------------------------------------------------------------
// Pre-pass: convert weights fp32 -> fp16
// ---------------------------------------------------------------------------
__global__ __launch_bounds__(256) void cvt_w_kernel(
    const float* __restrict__ in, __half* __restrict__ out, int n)
{
    int i = blockIdx.x * 256 + threadIdx.x;
    if (i < n) out[i] = __float2half_rn(in[i]);
}

// ---------------------------------------------------------------------------
// Pre-pass: x [B,C,N] -> Xb fp16 (same layout) + XT fp16 ([B,N,C])
// ---------------------------------------------------------------------------
__global__ __launch_bounds__(1024) void conv_x_kernel(
    const float* __restrict__ x,
    __half* __restrict__ xb, __half* __restrict__ xt)
{
    __shared__ float T[32][33];
    const int n0 = blockIdx.x * 32, c0 = blockIdx.y * 32, b = blockIdx.z;
    const int tx = threadIdx.x, ty = threadIdx.y;

    size_t src = ((size_t)(b * CH + c0 + ty) << 10) + n0 + tx;
    float v = x[src];
    xb[src] = __float2half_rn(v);
    T[ty][tx] = v;
    __syncthreads();
    float u = T[tx][ty];
    size_t dst = ((size_t)b * NTOK + n0 + ty) * CH + c0 + tx;
    xt[dst] = __float2half_rn(u);
}

// ---------------------------------------------------------------------------
// Softmax rows (fp32 in) -> fp16 probs out
// ---------------------------------------------------------------------------
__global__ __launch_bounds__(256) void softmax_h_kernel(
    const float* __restrict__ S, __half* __restrict__ P)
{
    const float4* row = reinterpret_cast<const float4*>(S + (size_t)blockIdx.x * NTOK);
    const int t = threadIdx.x;
    const int wid = t >> 5, lane = t & 31;

    float4 v = row[t];
    float m = fmaxf(fmaxf(v.x, v.y), fmaxf(v.z, v.w));
#pragma unroll
    for (int o = 16; o > 0; o >>= 1) m = fmaxf(m, __shfl_xor_sync(0xffffffffu, m, o));

    __shared__ float sred[8];
    __shared__ float sbc;
    if (!lane) sred[wid] = m;
    __syncthreads();
    if (t == 0) {
        float mm = sred[0];
#pragma unroll
        for (int i = 1; i < 8; i++) mm = fmaxf(mm, sred[i]);
        sbc = mm;
    }
    __syncthreads();
    m = sbc;

    v.x = __expf(v.x - m); v.y = __expf(v.y - m);
    v.z = __expf(v.z - m); v.w = __expf(v.w - m);
    float s = v.x + v.y + v.z + v.w;
#pragma unroll
    for (int o = 16; o > 0; o >>= 1) s += __shfl_xor_sync(0xffffffffu, s, o);
    __syncthreads();
    if (!lane) sred[wid] = s;
    __syncthreads();
    if (t == 0) {
        float ss = 0.f;
#pragma unroll
        for (int i = 0; i < 8; i++) ss += sred[i];
        sbc = 1.0f / ss;
    }
    __syncthreads();
    float inv = sbc;

    __half2 p01 = __floats2half2_rn(v.x * inv, v.y * inv);
    __half2 p23 = __floats2half2_rn(v.z * inv, v.w * inv);
    size_t base = (size_t)blockIdx.x * NTOK + t * 4;
    *reinterpret_cast<uint2*>(P + base) =
        make_uint2(*reinterpret_cast<uint32_t*>(&p01), *reinterpret_cast<uint32_t*>(&p23));
}

// ---------------------------------------------------------------------------
// HMMA fp16 NT GEMM: D[i][j] = sum_k A[i,k]*B[j,k]
// CTA 128x128, 4 warps (2x2), warp tile 64x64, BK=64, 3-stage cp.async ring.
// SMEM stage: A @0 (16KB), B @16K (16KB) -> 32KB/stage, rows 128B wide.
// Swizzle: phys(row,chunk16B) = row*128 + ((chunk ^ (row&7))*16)
// Inner loop: bf loaded 4 regs at a time (t-loop) to let ptxas overlap
// ldsm(t+1) with mma(t) and cut register live ranges.
// MODE 1: store fp16                MODE 2: +bias relu, fp16
// MODE 3: +bias +resid, fp32 transposed [B,C,N]
// MODE 4: symmetric scores: grid.x = triangular tile index (bm<=bn);
//         store fp32*SCALE at (bm,bn); if bm!=bn also mirrored at (bn,bm)
//         via 129-stride smem transpose.
// ---------------------------------------------------------------------------
#define STAGE_BYTES 32768
#define NSTAGE 3
#define SMEM_BYTES (NSTAGE * STAGE_BYTES)
#define NTILES 8   // NTOK/128

template <int MODE>
__global__ void __launch_bounds__(128, 1) gemm_hmma(
    const __half* __restrict__ A, int lda, size_t sAz,
    const __half* __restrict__ B, int ldb, size_t sBz,
    int K,
    float* __restrict__ outF, __half* __restrict__ outH,
    int ldo, size_t sOz,
    const float* __restrict__ bias, const float* __restrict__ resid)
{
    extern __shared__ char smem[];
    const uint32_t sb = smem_u32(smem);

    const int tid  = threadIdx.x;
    const int lane = tid & 31;
    const int w    = tid >> 5;     // 0..3
    const int wm   = w & 1;        // 0..1 : 64-row slab
    const int wn   = w >> 1;       // 0..1 : 64-col slab

    int i0, j0, bm = 0, bn = 0;
    if (MODE == 4) {
        int t = blockIdx.x;
        while (t >= NTILES - bm) { t -= (NTILES - bm); bm++; }
        bn = bm + t;
        i0 = bm * 128; j0 = bn * 128;
    } else {
        i0 = blockIdx.x * 128;
        j0 = blockIdx.y * 128;
    }
    const int z = blockIdx.z;

    // ---- cp.async mapping: thread -> (row rw 0..15, 16B chunk ch 0..7)
    const int ch = tid & 7;
    const int rw = tid >> 3;                                  // 0..15
    const uint32_t sbase = (uint32_t)rw * 128u + (uint32_t)((ch ^ (rw & 7)) << 4);

    const __half* gA = A + (size_t)z * sAz + (size_t)(i0 + rw) * lda + ch * 8;
    const __half* gB = B + (size_t)z * sBz + (size_t)(j0 + rw) * ldb + ch * 8;

    // ---- ldmatrix geometry (within 64x64 warp tile)
    const int rA = wm * 64 + ((lane >> 3) & 1) * 8 + (lane & 7);   // A row (+16 per mi)
    const int rB = wn * 64 + ((lane >> 4) << 3) + (lane & 7);      // B row (+16 per t)
    const int swA = rA & 7;
    const int swB = rB & 7;
    const uint32_t rowA = (uint32_t)rA * 128u;
    const uint32_t rowB = (uint32_t)rB * 128u;

    float acc[128];
#pragma unroll
    for (int i = 0; i < 128; i++) acc[i] = 0.f;

    const int NC = K >> 6;    // BK=64

    // issue one BK=64 stage: A(16KB)+B(16KB); each thread 8+8 cp.async of 16B
    auto issue = [&](int c, int st) {
        const uint32_t base = sb + (uint32_t)st * STAGE_BYTES;
        const int ko = c << 6;
#pragma unroll
        for (int it = 0; it < 8; it++)
            cpa16(base + sbase + it * 2048u, gA + ko + (size_t)(it * 16) * lda);
#pragma unroll
        for (int it = 0; it < 8; it++)
            cpa16(base + 16384u + sbase + it * 2048u, gB + ko + (size_t)(it * 16) * ldb);
    };

    issue(0, 0); CP_COMMIT();
    issue(1, 1); CP_COMMIT();

    int st_use = 0, st_pf = 2;
    for (int c = 0; c < NC; c++) {
        CP_WAIT1();
        __syncthreads();
        if (c + 2 < NC) issue(c + 2, st_pf);
        CP_COMMIT();

        const uint32_t tb = sb + (uint32_t)st_use * STAGE_BYTES;
#pragma unroll
        for (int ks = 0; ks < 4; ks++) {
            const int cA = ks * 2 + (lane >> 4);
            const int cB = ks * 2 + ((lane >> 3) & 1);
            const uint32_t aA = tb + rowA + (uint32_t)(((cA ^ swA) << 4));
            const uint32_t bB = tb + 16384u + rowB + (uint32_t)(((cB ^ swB) << 4));

            uint32_t af[16];
#pragma unroll
            for (int mi = 0; mi < 4; mi++)
                ldsm4(aA + mi * 2048u, af[mi*4+0], af[mi*4+1], af[mi*4+2], af[mi*4+3]);
#pragma unroll
            for (int t = 0; t < 4; t++) {
                uint32_t bq[4];
                ldsm4(bB + t * 2048u, bq[0], bq[1], bq[2], bq[3]);
#pragma unroll
                for (int mi = 0; mi < 4; mi++) {
                    mma16816(&acc[(mi*8 + 2*t + 0)*4], &af[mi*4], &bq[0]);
                    mma16816(&acc[(mi*8 + 2*t + 1)*4], &af[mi*4], &bq[2]);
                }
            }
        }
        st_use = (st_use == NSTAGE - 1) ? 0 : st_use + 1;
        st_pf  = (st_pf  == NSTAGE - 1) ? 0 : st_pf  + 1;
    }

    // ------------------- epilogue (registers -> gmem) -------------------
#pragma unroll
    for (int mi = 0; mi < 4; mi++) {
        const int r0 = i0 + wm * 64 + mi * 16 + (lane >> 2);
        const int r1 = r0 + 8;
#pragma unroll
        for (int ni = 0; ni < 8; ni++) {
            const float* a = &acc[(mi*8+ni)*4];
            const int c0 = j0 + wn * 64 + ni * 8 + (lane & 3) * 2;

            if (MODE == 4) {
                float* C = outF + (size_t)z * sOz;
                *reinterpret_cast<float2*>(C + (size_t)r0 * ldo + c0) =
                    make_float2(a[0] * SCALE, a[1] * SCALE);
                *reinterpret_cast<float2*>(C + (size_t)r1 * ldo + c0) =
                    make_float2(a[2] * SCALE, a[3] * SCALE);
            } else if (MODE == 1 || MODE == 2) {
                float v0 = a[0], v1 = a[1], v2 = a[2], v3 = a[3];
                if (MODE == 2) {
                    float bj0 = __ldg(bias + c0), bj1 = __ldg(bias + c0 + 1);
                    v0 = fmaxf(v0 + bj0, 0.f); v1 = fmaxf(v1 + bj1, 0.f);
                    v2 = fmaxf(v2 + bj0, 0.f); v3 = fmaxf(v3 + bj1, 0.f);
                }
                const size_t o0 = (size_t)z * sOz + (size_t)r0 * ldo + c0;
                const size_t o1 = (size_t)z * sOz + (size_t)r1 * ldo + c0;
                __half2 p0 = __floats2half2_rn(v0, v1);
                __half2 p1 = __floats2half2_rn(v2, v3);
                *reinterpret_cast<uint32_t*>(outH + o0) = *reinterpret_cast<uint32_t*>(&p0);
                *reinterpret_cast<uint32_t*>(outH + o1) = *reinterpret_cast<uint32_t*>(&p1);
            } else if (MODE == 3) {
                // out[b, c, n] = D + bias[c] + resid
                const int b  = r0 >> 10;
                const int n0 = r0 & (NTOK - 1);
                const int n1 = n0 + 8;
                const float bj0 = __ldg(bias + c0), bj1 = __ldg(bias + c0 + 1);
                const size_t base0 = ((size_t)(b * CH + c0) << 10);
                outF[base0 + n0]        = a[0] + bj0 + __ldg(resid + base0 + n0);
                outF[base0 + 1024 + n0] = a[1] + bj1 + __ldg(resid + base0 + 1024 + n0);
                outF[base0 + n1]        = a[2] + bj0 + __ldg(resid + base0 + n1);
                outF[base0 + 1024 + n1] = a[3] + bj1 + __ldg(resid + base0 + 1024 + n1);
            }
        }
    }

    // ---- MODE 4 mirrored tile: S[bn-tile][bm-tile] = tile^T via smem ----
    if (MODE == 4) {
        if (bm == bn) return;
        float* Ts = reinterpret_cast<float*>(smem);   // 128 x 128, stride 129
        __syncthreads();   // mainloop smem no longer needed by any warp
#pragma unroll
        for (int mi = 0; mi < 4; mi++) {
            const int lr0 = wm * 64 + mi * 16 + (lane >> 2);
#pragma unroll
            for (int ni = 0; ni < 8; ni++) {
                const float* a = &acc[(mi*8+ni)*4];
                const int lc0 = wn * 64 + ni * 8 + (lane & 3) * 2;
                Ts[lr0 * 129 + lc0]           = a[0] * SCALE;
                Ts[lr0 * 129 + lc0 + 1]       = a[1] * SCALE;
                Ts[(lr0 + 8) * 129 + lc0]     = a[2] * SCALE;
                Ts[(lr0 + 8) * 129 + lc0 + 1] = a[3] * SCALE;
            }
        }
        __syncthreads();
        // write transposed: out[(j0 + i)*ldo + (i0 + j)] = Ts[i*129 + j]
        float* C = outF + (size_t)z * sOz;
#pragma unroll
        for (int q = 0; q < 4; q++) {
            const int j = lane + 32 * q;
#pragma unroll
            for (int ii = 0; ii < 32; ii++) {
                const int i = (tid >> 5) + ii * 4;
                C[(size_t)(j0 + i) * ldo + i0 + j] = Ts[i * 129 + j];
            }
        }
    }
}

// ---------------------------------------------------------------------------
extern "C" void kernel_launch(void* const* d_in, const int* in_sizes, int n_in,
                              void* d_out, int out_size)
{
    const float* x  = (const float*)d_in[0];
    const float* w1 = (const float*)d_in[1];
    const float* b1 = (const float*)d_in[2];
    const float* w2 = (const float*)d_in[3];
    const float* b2 = (const float*)d_in[4];
    float* out = (float*)d_out;

    float *S;
    __half *P, *XT, *Xb, *O, *H, *w1h, *w2h;
    cudaGetSymbolAddress((void**)&S,   g_S);
    cudaGetSymbolAddress((void**)&P,   g_P);
    cudaGetSymbolAddress((void**)&XT,  g_XT);
    cudaGetSymbolAddress((void**)&Xb,  g_Xb);
    cudaGetSymbolAddress((void**)&O,   g_O);
    cudaGetSymbolAddress((void**)&H,   g_H);
    cudaGetSymbolAddress((void**)&w1h, g_w1);
    cudaGetSymbolAddress((void**)&w2h, g_w2);

    cudaFuncSetAttribute(gemm_hmma<4>, cudaFuncAttributeMaxDynamicSharedMemorySize, SMEM_BYTES);
    cudaFuncSetAttribute(gemm_hmma<1>, cudaFuncAttributeMaxDynamicSharedMemorySize, SMEM_BYTES);
    cudaFuncSetAttribute(gemm_hmma<2>, cudaFuncAttributeMaxDynamicSharedMemorySize, SMEM_BYTES);
    cudaFuncSetAttribute(gemm_hmma<3>, cudaFuncAttributeMaxDynamicSharedMemorySize, SMEM_BYTES);

    // pre-pass: convert weights + x to fp16
    cvt_w_kernel<<<(HID * CH + 255) / 256, 256>>>(w1, w1h, HID * CH);
    cvt_w_kernel<<<(CH * HID + 255) / 256, 256>>>(w2, w2h, CH * HID);
    conv_x_kernel<<<dim3(NTOK / 32, CH / 32, BATCH), dim3(32, 32)>>>(x, Xb, XT);

    // 1) S = SCALE * XT @ XT^T  (symmetric: 36 upper-triangle tile pairs)
    gemm_hmma<4><<<dim3(NTILES * (NTILES + 1) / 2, 1, BATCH), 128, SMEM_BYTES>>>(
        XT, CH, (size_t)NTOK * CH,
        XT, CH, (size_t)NTOK * CH,
        CH, S, nullptr, NTOK, (size_t)NTOK * NTOK, nullptr, nullptr);

    // 2) softmax -> fp16 probs
    softmax_h_kernel<<<BATCH * NTOK, 256>>>(S, P);

    // 3) O = P @ X^T              [B*N, C]
    gemm_hmma<1><<<dim3(NTOK / 128, CH / 128, BATCH), 128, SMEM_BYTES>>>(
        P, NTOK, (size_t)NTOK * NTOK,
        Xb, NTOK, (size_t)CH * NTOK,
        NTOK, nullptr, O, CH, (size_t)NTOK * CH, nullptr, nullptr);

    // 4) H = relu(O @ w1^T + b1)  [B*N, HID]
    gemm_hmma<2><<<dim3(BATCH * NTOK / 128, HID / 128, 1), 128, SMEM_BYTES>>>(
        O, CH, 0,
        w1h, CH, 0,
        CH, nullptr, H, HID, 0, b1, nullptr);

    // 5) y = H @ w2^T + b2 (+x), transposed store -> out [B, C, H, W]
    gemm_hmma<3><<<dim3(BATCH * NTOK / 128, CH / 128, 1), 128, SMEM_BYTES>>>(
        H, HID, 0,
        w2h, HID, 0,
        HID, out, nullptr, CH, 0, b2, x);
}

// round 12
// speedup vs baseline: 8.6293x; 1.0044x over previous
#include <cuda_runtime.h>
#include <cuda_fp16.h>
#include <cstdint>

// Problem constants
#define BATCH 16
#define CH    512
#define NTOK  1024
#define HID   2048
#define SCALE 0.04419417382415922f   // 512^-0.5

// ---------------------------------------------------------------------------
// Static device scratch
// ---------------------------------------------------------------------------
__device__ __half  g_P [(size_t)BATCH * NTOK * NTOK];   // unnormalized probs fp16
__device__ __half  g_XT[(size_t)BATCH * NTOK * CH];     // X^T [B,N,C]
__device__ __half  g_Xb[(size_t)BATCH * CH * NTOK];     // X   [B,C,N]
__device__ __half  g_O [(size_t)BATCH * NTOK * CH];     // attn out [B*N, C]
__device__ __half  g_H [(size_t)BATCH * NTOK * HID];    // hidden   [B*N, HID]
__device__ __half  g_w1[(size_t)HID * CH];
__device__ __half  g_w2[(size_t)CH * HID];
__device__ float   g_rnp[(size_t)BATCH * NTOK * 16];    // rownorm partials
__device__ float   g_rn [(size_t)BATCH * NTOK];         // rn = SCALE*||x_n||^2
__device__ float   g_rsi[(size_t)BATCH * NTOK];         // 1 / rowsum(P')

// ---------------------------------------------------------------------------
// Helpers (baseline PTX, valid at compute_103)
// ---------------------------------------------------------------------------
__device__ __forceinline__ uint32_t smem_u32(const void* p) {
    uint32_t a;
    asm("{ .reg .u64 t; cvta.to.shared.u64 t, %1; cvt.u32.u64 %0, t; }" : "=r"(a) : "l"(p));
    return a;
}
__device__ __forceinline__ void cpa16(uint32_t d, const void* s) {
    asm volatile("cp.async.cg.shared.global [%0], [%1], 16;" :: "r"(d), "l"(s));
}
#define CP_COMMIT() asm volatile("cp.async.commit_group;" ::: "memory")
#define CP_WAIT1()  asm volatile("cp.async.wait_group 1;" ::: "memory")

__device__ __forceinline__ void ldsm4(uint32_t a, uint32_t& r0, uint32_t& r1,
                                      uint32_t& r2, uint32_t& r3) {
    asm volatile("ldmatrix.sync.aligned.m8n8.x4.shared.b16 {%0,%1,%2,%3}, [%4];"
                 : "=r"(r0), "=r"(r1), "=r"(r2), "=r"(r3) : "r"(a));
}
__device__ __forceinline__ void mma16816(float* d, const uint32_t* a, const uint32_t* b) {
    asm volatile("mma.sync.aligned.m16n8k16.row.col.f32.f16.f16.f32 "
                 "{%0,%1,%2,%3}, {%4,%5,%6,%7}, {%8,%9}, {%0,%1,%2,%3};"
                 : "+f"(d[0]), "+f"(d[1]), "+f"(d[2]), "+f"(d[3])
                 : "r"(a[0]), "r"(a[1]), "r"(a[2]), "r"(a[3]), "r"(b[0]), "r"(b[1]));
}

// ---------------------------------------------------------------------------
// Pre-pass: convert weights fp32 -> fp16
// ---------------------------------------------------------------------------
__global__ __launch_bounds__(256) void cvt_w_kernel(
    const float* __restrict__ in, __half* __restrict__ out, int n)
{
    int i = blockIdx.x * 256 + threadIdx.x;
    if (i < n) out[i] = __float2half_rn(in[i]);
}

// ---------------------------------------------------------------------------
// Pre-pass: x [B,C,N] -> Xb fp16 + XT fp16 + rownorm partials
// ---------------------------------------------------------------------------
__global__ __launch_bounds__(1024) void conv_x_kernel(
    const float* __restrict__ x,
    __half* __restrict__ xb, __half* __restrict__ xt,
    float* __restrict__ rnp)
{
    __shared__ float T[32][33];
    const int n0 = blockIdx.x * 32, c0 = blockIdx.y * 32, b = blockIdx.z;
    const int tx = threadIdx.x, ty = threadIdx.y;

    size_t src = ((size_t)(b * CH + c0 + ty) << 10) + n0 + tx;
    float v = x[src];
    xb[src] = __float2half_rn(v);
    T[ty][tx] = v;
    __syncthreads();
    float u = T[tx][ty];
    size_t dst = ((size_t)b * NTOK + n0 + ty) * CH + c0 + tx;
    xt[dst] = __float2half_rn(u);

    // partial rownorm for the 32 tokens of this tile over these 32 channels
    if (ty == 0) {
        float s = 0.f;
#pragma unroll
        for (int c = 0; c < 32; c++) { float t = T[c][tx]; s += t * t; }
        rnp[((size_t)(b * NTOK + n0 + tx) << 4) + blockIdx.y] = s;
    }
}

// ---------------------------------------------------------------------------
// rn[i] = SCALE * sum of 16 partials   (deterministic)
// ---------------------------------------------------------------------------
__global__ __launch_bounds__(256) void reduce_rn_kernel(
    const float* __restrict__ rnp, float* __restrict__ rn)
{
    int i = blockIdx.x * 256 + threadIdx.x;   // 0..16383
    float s = 0.f;
#pragma unroll
    for (int j = 0; j < 16; j++) s += rnp[((size_t)i << 4) + j];
    rn[i] = s * SCALE;
}

// ---------------------------------------------------------------------------
// rsi[row] = 1 / sum_m P'[row, m]   (deterministic block reduction)
// ---------------------------------------------------------------------------
__global__ __launch_bounds__(256) void rowinv_kernel(
    const __half* __restrict__ P, float* __restrict__ rsi)
{
    const uint2* row = reinterpret_cast<const uint2*>(P + (size_t)blockIdx.x * NTOK);
    const int t = threadIdx.x;
    const int wid = t >> 5, lane = t & 31;

    uint2 v = row[t];
    __half2 a = *reinterpret_cast<__half2*>(&v.x);
    __half2 b = *reinterpret_cast<__half2*>(&v.y);
    float2 fa = __half22float2(a), fb = __half22float2(b);
    float s = fa.x + fa.y + fb.x + fb.y;
#pragma unroll
    for (int o = 16; o > 0; o >>= 1) s += __shfl_xor_sync(0xffffffffu, s, o);

    __shared__ float sred[8];
    if (!lane) sred[wid] = s;
    __syncthreads();
    if (t == 0) {
        float ss = 0.f;
#pragma unroll
        for (int i = 0; i < 8; i++) ss += sred[i];
        rsi[blockIdx.x] = 1.0f / ss;
    }
}

// ---------------------------------------------------------------------------
// HMMA fp16 NT GEMM: D[i][j] = sum_k A[i,k]*B[j,k]
// CTA 128x128, 4 warps (2x2), warp tile 64x64, BK=64, 3-stage cp.async ring.
// SMEM stage: A @0 (16KB), B @16K (16KB) -> 32KB/stage, rows 128B wide.
// Swizzle: phys(row,chunk16B) = row*128 + ((chunk ^ (row&7))*16)
// MODE 1: store fp16 scaled by rsi[row]   (attn PV, normalization fused)
// MODE 2: +bias relu, fp16                (FFN1)
// MODE 3: +bias +resid, fp32 transposed [B,C,N]  (FFN2 + residual)
// MODE 4: symmetric scores -> P' = exp(s*SCALE - rn[row]) fp16 at (bm,bn),
//         mirrored tile (bn,bm) via 129-stride smem transpose, exp w/ its row rn.
//         bias arg = rn array.   MODE 1: resid arg = rsi array.
// ---------------------------------------------------------------------------
#define STAGE_BYTES 32768
#define NSTAGE 3
#define SMEM_BYTES (NSTAGE * STAGE_BYTES)
#define NTILES 8   // NTOK/128

template <int MODE>
__global__ void __launch_bounds__(128, 1) gemm_hmma(
    const __half* __restrict__ A, int lda, size_t sAz,
    const __half* __restrict__ B, int ldb, size_t sBz,
    int K,
    float* __restrict__ outF, __half* __restrict__ outH,
    int ldo, size_t sOz,
    const float* __restrict__ bias, const float* __restrict__ resid)
{
    extern __shared__ char smem[];
    const uint32_t sb = smem_u32(smem);

    const int tid  = threadIdx.x;
    const int lane = tid & 31;
    const int w    = tid >> 5;     // 0..3
    const int wm   = w & 1;        // 0..1 : 64-row slab
    const int wn   = w >> 1;       // 0..1 : 64-col slab

    int i0, j0, bm = 0, bn = 0;
    if (MODE == 4) {
        int t = blockIdx.x;
        while (t >= NTILES - bm) { t -= (NTILES - bm); bm++; }
        bn = bm + t;
        i0 = bm * 128; j0 = bn * 128;
    } else {
        i0 = blockIdx.x * 128;
        j0 = blockIdx.y * 128;
    }
    const int z = blockIdx.z;

    // ---- cp.async mapping: thread -> (row rw 0..15, 16B chunk ch 0..7)
    const int ch = tid & 7;
    const int rw = tid >> 3;                                  // 0..15
    const uint32_t sbase = (uint32_t)rw * 128u + (uint32_t)((ch ^ (rw & 7)) << 4);

    const __half* gA = A + (size_t)z * sAz + (size_t)(i0 + rw) * lda + ch * 8;
    const __half* gB = B + (size_t)z * sBz + (size_t)(j0 + rw) * ldb + ch * 8;

    // ---- ldmatrix geometry (within 64x64 warp tile)
    const int rA = wm * 64 + ((lane >> 3) & 1) * 8 + (lane & 7);   // A row (+16 per mi)
    const int rB = wn * 64 + ((lane >> 4) << 3) + (lane & 7);      // B row (+16 per t)
    const int swA = rA & 7;
    const int swB = rB & 7;
    const uint32_t rowA = (uint32_t)rA * 128u;
    const uint32_t rowB = (uint32_t)rB * 128u;

    float acc[128];
#pragma unroll
    for (int i = 0; i < 128; i++) acc[i] = 0.f;

    const int NC = K >> 6;    // BK=64

    auto issue = [&](int c, int st) {
        const uint32_t base = sb + (uint32_t)st * STAGE_BYTES;
        const int ko = c << 6;
#pragma unroll
        for (int it = 0; it < 8; it++)
            cpa16(base + sbase + it * 2048u, gA + ko + (size_t)(it * 16) * lda);
#pragma unroll
        for (int it = 0; it < 8; it++)
            cpa16(base + 16384u + sbase + it * 2048u, gB + ko + (size_t)(it * 16) * ldb);
    };

    issue(0, 0); CP_COMMIT();
    issue(1, 1); CP_COMMIT();

    int st_use = 0, st_pf = 2;
    for (int c = 0; c < NC; c++) {
        CP_WAIT1();
        __syncthreads();
        if (c + 2 < NC) issue(c + 2, st_pf);
        CP_COMMIT();

        const uint32_t tb = sb + (uint32_t)st_use * STAGE_BYTES;
#pragma unroll
        for (int ks = 0; ks < 4; ks++) {
            const int cA = ks * 2 + (lane >> 4);
            const int cB = ks * 2 + ((lane >> 3) & 1);
            const uint32_t aA = tb + rowA + (uint32_t)(((cA ^ swA) << 4));
            const uint32_t bB = tb + 16384u + rowB + (uint32_t)(((cB ^ swB) << 4));

            uint32_t af[16];
#pragma unroll
            for (int mi = 0; mi < 4; mi++)
                ldsm4(aA + mi * 2048u, af[mi*4+0], af[mi*4+1], af[mi*4+2], af[mi*4+3]);
#pragma unroll
            for (int t = 0; t < 4; t++) {
                uint32_t bq[4];
                ldsm4(bB + t * 2048u, bq[0], bq[1], bq[2], bq[3]);
#pragma unroll
                for (int mi = 0; mi < 4; mi++) {
                    mma16816(&acc[(mi*8 + 2*t + 0)*4], &af[mi*4], &bq[0]);
                    mma16816(&acc[(mi*8 + 2*t + 1)*4], &af[mi*4], &bq[2]);
                }
            }
        }
        st_use = (st_use == NSTAGE - 1) ? 0 : st_use + 1;
        st_pf  = (st_pf  == NSTAGE - 1) ? 0 : st_pf  + 1;
    }

    // ------------------- epilogue (registers -> gmem) -------------------
#pragma unroll
    for (int mi = 0; mi < 4; mi++) {
        const int r0 = i0 + wm * 64 + mi * 16 + (lane >> 2);
        const int r1 = r0 + 8;
        float rn0 = 0.f, rn1 = 0.f, inv0 = 1.f, inv1 = 1.f;
        if (MODE == 4) {
            rn0 = __ldg(bias + (size_t)z * NTOK + r0);
            rn1 = __ldg(bias + (size_t)z * NTOK + r1);
        }
        if (MODE == 1) {
            inv0 = __ldg(resid + (size_t)z * NTOK + r0);
            inv1 = __ldg(resid + (size_t)z * NTOK + r1);
        }
#pragma unroll
        for (int ni = 0; ni < 8; ni++) {
            const float* a = &acc[(mi*8+ni)*4];
            const int c0 = j0 + wn * 64 + ni * 8 + (lane & 3) * 2;

            if (MODE == 4) {
                // P' = exp(score - rn[row]) stored fp16
                float e00 = __expf(a[0] * SCALE - rn0);
                float e01 = __expf(a[1] * SCALE - rn0);
                float e10 = __expf(a[2] * SCALE - rn1);
                float e11 = __expf(a[3] * SCALE - rn1);
                const size_t o0 = (size_t)z * sOz + (size_t)r0 * ldo + c0;
                const size_t o1 = (size_t)z * sOz + (size_t)r1 * ldo + c0;
                __half2 p0 = __floats2half2_rn(e00, e01);
                __half2 p1 = __floats2half2_rn(e10, e11);
                *reinterpret_cast<uint32_t*>(outH + o0) = *reinterpret_cast<uint32_t*>(&p0);
                *reinterpret_cast<uint32_t*>(outH + o1) = *reinterpret_cast<uint32_t*>(&p1);
            } else if (MODE == 1 || MODE == 2) {
                float v0 = a[0], v1 = a[1], v2 = a[2], v3 = a[3];
                if (MODE == 1) {
                    v0 *= inv0; v1 *= inv0; v2 *= inv1; v3 *= inv1;
                }
                if (MODE == 2) {
                    float bj0 = __ldg(bias + c0), bj1 = __ldg(bias + c0 + 1);
                    v0 = fmaxf(v0 + bj0, 0.f); v1 = fmaxf(v1 + bj1, 0.f);
                    v2 = fmaxf(v2 + bj0, 0.f); v3 = fmaxf(v3 + bj1, 0.f);
                }
                const size_t o0 = (size_t)z * sOz + (size_t)r0 * ldo + c0;
                const size_t o1 = (size_t)z * sOz + (size_t)r1 * ldo + c0;
                __half2 p0 = __floats2half2_rn(v0, v1);
                __half2 p1 = __floats2half2_rn(v2, v3);
                *reinterpret_cast<uint32_t*>(outH + o0) = *reinterpret_cast<uint32_t*>(&p0);
                *reinterpret_cast<uint32_t*>(outH + o1) = *reinterpret_cast<uint32_t*>(&p1);
            } else if (MODE == 3) {
                // out[b, c, n] = D + bias[c] + resid
                const int b  = r0 >> 10;
                const int n0 = r0 & (NTOK - 1);
                const int n1 = n0 + 8;
                const float bj0 = __ldg(bias + c0), bj1 = __ldg(bias + c0 + 1);
                const size_t base0 = ((size_t)(b * CH + c0) << 10);
                outF[base0 + n0]        = a[0] + bj0 + __ldg(resid + base0 + n0);
                outF[base0 + 1024 + n0] = a[1] + bj1 + __ldg(resid + base0 + 1024 + n0);
                outF[base0 + n1]        = a[2] + bj0 + __ldg(resid + base0 + n1);
                outF[base0 + 1024 + n1] = a[3] + bj1 + __ldg(resid + base0 + 1024 + n1);
            }
        }
    }

    // ---- MODE 4 mirrored tile: P'[bn-rows, bm-cols] = exp(s^T - rn[row]) ----
    if (MODE == 4) {
        if (bm == bn) return;
        float* Ts = reinterpret_cast<float*>(smem);   // 128 x 128, stride 129
        __syncthreads();   // mainloop smem no longer needed by any warp
#pragma unroll
        for (int mi = 0; mi < 4; mi++) {
            const int lr0 = wm * 64 + mi * 16 + (lane >> 2);
#pragma unroll
            for (int ni = 0; ni < 8; ni++) {
                const float* a = &acc[(mi*8+ni)*4];
                const int lc0 = wn * 64 + ni * 8 + (lane & 3) * 2;
                Ts[lr0 * 129 + lc0]           = a[0] * SCALE;
                Ts[lr0 * 129 + lc0 + 1]       = a[1] * SCALE;
                Ts[(lr0 + 8) * 129 + lc0]     = a[2] * SCALE;
                Ts[(lr0 + 8) * 129 + lc0 + 1] = a[3] * SCALE;
            }
        }
        __syncthreads();
        // P'[(j0+i), i0+j] = exp(Ts[i][j] - rn[j0+i]); half2 stores on j pairs
#pragma unroll
        for (int ii = 0; ii < 32; ii++) {
            const int i = (tid >> 5) + ii * 4;
            const int row = j0 + i;
            const float rnv = __ldg(bias + (size_t)z * NTOK + row);
#pragma unroll
            for (int q = 0; q < 2; q++) {
                const int jj = (lane + 32 * q) * 2;
                float v0 = Ts[i * 129 + jj];
                float v1 = Ts[i * 129 + jj + 1];
                __half2 p = __floats2half2_rn(__expf(v0 - rnv), __expf(v1 - rnv));
                *reinterpret_cast<uint32_t*>(
                    outH + (size_t)z * sOz + (size_t)row * ldo + i0 + jj) =
                    *reinterpret_cast<uint32_t*>(&p);
            }
        }
    }
}

// ---------------------------------------------------------------------------
extern "C" void kernel_launch(void* const* d_in, const int* in_sizes, int n_in,
                              void* d_out, int out_size)
{
    const float* x  = (const float*)d_in[0];
    const float* w1 = (const float*)d_in[1];
    const float* b1 = (const float*)d_in[2];
    const float* w2 = (const float*)d_in[3];
    const float* b2 = (const float*)d_in[4];
    float* out = (float*)d_out;

    __half *P, *XT, *Xb, *O, *H, *w1h, *w2h;
    float *RNP, *RN, *RSI;
    cudaGetSymbolAddress((void**)&P,   g_P);
    cudaGetSymbolAddress((void**)&XT,  g_XT);
    cudaGetSymbolAddress((void**)&Xb,  g_Xb);
    cudaGetSymbolAddress((void**)&O,   g_O);
    cudaGetSymbolAddress((void**)&H,   g_H);
    cudaGetSymbolAddress((void**)&w1h, g_w1);
    cudaGetSymbolAddress((void**)&w2h, g_w2);
    cudaGetSymbolAddress((void**)&RNP, g_rnp);
    cudaGetSymbolAddress((void**)&RN,  g_rn);
    cudaGetSymbolAddress((void**)&RSI, g_rsi);

    cudaFuncSetAttribute(gemm_hmma<4>, cudaFuncAttributeMaxDynamicSharedMemorySize, SMEM_BYTES);
    cudaFuncSetAttribute(gemm_hmma<1>, cudaFuncAttributeMaxDynamicSharedMemorySize, SMEM_BYTES);
    cudaFuncSetAttribute(gemm_hmma<2>, cudaFuncAttributeMaxDynamicSharedMemorySize, SMEM_BYTES);
    cudaFuncSetAttribute(gemm_hmma<3>, cudaFuncAttributeMaxDynamicSharedMemorySize, SMEM_BYTES);

    // pre-pass: convert weights + x to fp16; rownorm partials + reduce
    cvt_w_kernel<<<(HID * CH + 255) / 256, 256>>>(w1, w1h, HID * CH);
    cvt_w_kernel<<<(CH * HID + 255) / 256, 256>>>(w2, w2h, CH * HID);
    conv_x_kernel<<<dim3(NTOK / 32, CH / 32, BATCH), dim3(32, 32)>>>(x, Xb, XT, RNP);
    reduce_rn_kernel<<<BATCH * NTOK / 256, 256>>>(RNP, RN);

    // 1) P' = exp(SCALE * XT @ XT^T - rn[row])  (symmetric, 36 tile pairs)
    gemm_hmma<4><<<dim3(NTILES * (NTILES + 1) / 2, 1, BATCH), 128, SMEM_BYTES>>>(
        XT, CH, (size_t)NTOK * CH,
        XT, CH, (size_t)NTOK * CH,
        CH, nullptr, P, NTOK, (size_t)NTOK * NTOK, RN, nullptr);

    // 2) row inverse sums of P'
    rowinv_kernel<<<BATCH * NTOK, 256>>>(P, RSI);

    // 3) O = (P' @ X^T) * rsi[row]   [B*N, C]
    gemm_hmma<1><<<dim3(NTOK / 128, CH / 128, BATCH), 128, SMEM_BYTES>>>(
        P, NTOK, (size_t)NTOK * NTOK,
        Xb, NTOK, (size_t)CH * NTOK,
        NTOK, nullptr, O, CH, (size_t)NTOK * CH, nullptr, RSI);

    // 4) H = relu(O @ w1^T + b1)  [B*N, HID]
    gemm_hmma<2><<<dim3(BATCH * NTOK / 128, HID / 128, 1), 128, SMEM_BYTES>>>(
        O, CH, 0,
        w1h, CH, 0,
        CH, nullptr, H, HID, 0, b1, nullptr);

    // 5) y = H @ w2^T + b2 (+x), transposed store -> out [B, C, H, W]
    gemm_hmma<3><<<dim3(BATCH * NTOK / 128, CH / 128, 1), 128, SMEM_BYTES>>>(
        H, HID, 0,
        w2h, HID, 0,
        HID, out, nullptr, CH, 0, b2, x);
}